// round 13
// baseline (speedup 1.0000x reference)
#include <cuda_runtime.h>
#include <cuda_fp16.h>
#include <math.h>
#include <float.h>
#include <stdint.h>

// ---------------------------------------------------------------------------
// Problem constants
// ---------------------------------------------------------------------------
#define M_BAG   100000
#define M_PAD   100096          // 782 * 128 = 1564 * 64
#define NFEAT   1024
#define NCOMP   512
#define NHID    256

// Output layout (flattened reference tuple, fp32)
#define OFF_ATT   0u
#define OFF_A     200000u
#define OFF_H     400000u
#define OFF_LAB   51600000u
#define OFF_IU    51600016u
#define OFF_IL    51600048u
#define OFF_SS    51600080u
#define OFF_YP    51600082u
#define OFF_YH    51600084u

// ---------------------------------------------------------------------------
// Device scratch (static globals; allocation-free per harness rules)
// ---------------------------------------------------------------------------
__device__ __half g_hh[(size_t)M_PAD * NCOMP];    // h in fp16 (padded rows zero)
__device__ __half g_Wct[(size_t)NCOMP * NFEAT];   // Wc^T  [512][1024]
__device__ __half g_Wt12[(size_t)NCOMP * NCOMP];  // interleaved [W1|W2]^T [512][512]
__device__ float  g_AI[M_BAG];
__device__ float  g_agg[2 * NCOMP];
#define TK_BLOCKS 64
#define TK_CHUNK  1568
#define AGG_BLOCKS 1564
__device__ float  g_cmaxv[TK_BLOCKS * 8];
__device__ int    g_cmaxi[TK_BLOCKS * 8];
__device__ float  g_cminv[TK_BLOCKS * 8];
__device__ int    g_cmini[TK_BLOCKS * 8];

// ---------------------------------------------------------------------------
// PTX helpers (sm_80+ features only: mma.sync / ldmatrix / cp.async)
// ---------------------------------------------------------------------------
__device__ __forceinline__ uint32_t smem_u32(const void* p) {
    uint32_t a;
    asm("{ .reg .u64 t; cvta.to.shared.u64 t, %1; cvt.u32.u64 %0, t; }"
        : "=r"(a) : "l"(p));
    return a;
}

#define CPASYNC16(sa, gp) \
    asm volatile("cp.async.cg.shared.global [%0], [%1], 16;" \
                 :: "r"(sa), "l"(gp))
#define CPCOMMIT() asm volatile("cp.async.commit_group;")
template<int N> __device__ __forceinline__ void cp_wait() {
    asm volatile("cp.async.wait_group %0;" :: "n"(N));
}

__device__ __forceinline__ void ldsm4(uint32_t& r0, uint32_t& r1,
                                      uint32_t& r2, uint32_t& r3, uint32_t a) {
    asm volatile("ldmatrix.sync.aligned.m8n8.x4.shared.b16 {%0,%1,%2,%3}, [%4];"
                 : "=r"(r0), "=r"(r1), "=r"(r2), "=r"(r3) : "r"(a));
}

__device__ __forceinline__ void mma16816(float* c, const uint32_t* a,
                                         uint32_t b0, uint32_t b1) {
    asm volatile(
        "mma.sync.aligned.m16n8k16.row.col.f32.f16.f16.f32 "
        "{%0,%1,%2,%3}, {%4,%5,%6,%7}, {%8,%9}, {%0,%1,%2,%3};"
        : "+f"(c[0]), "+f"(c[1]), "+f"(c[2]), "+f"(c[3])
        : "r"(a[0]), "r"(a[1]), "r"(a[2]), "r"(a[3]), "r"(b0), "r"(b1));
}

__device__ __forceinline__ float tanha(float x) {
    float y; asm("tanh.approx.f32 %0, %1;" : "=f"(y) : "f"(x)); return y;
}

// ---------------------------------------------------------------------------
// Prep: coalesced tiled transposes (Wc^T, interleaved [W1|W2]^T) + zero g_agg
// grid = 769 blocks x 256 threads
// ---------------------------------------------------------------------------
__global__ __launch_bounds__(256)
void prep_kernel(const float* __restrict__ Wc,
                 const float* __restrict__ W1,
                 const float* __restrict__ W2)
{
    __shared__ float s[32][33];
    int b = blockIdx.x;
    int t = threadIdx.x;
    int r = t >> 5, c = t & 31;

    if (b < 512) {                         // Wc [1024x512] -> Wct [512][1024]
        int k0 = (b & 31) * 32;
        int n0 = (b >> 5) * 32;
        #pragma unroll
        for (int rr = 0; rr < 4; rr++)
            s[r + rr * 8][c] = Wc[(size_t)(k0 + r + rr * 8) * NCOMP + n0 + c];
        __syncthreads();
        #pragma unroll
        for (int rr = 0; rr < 4; rr++) {
            int nr = r + rr * 8;
            g_Wct[(size_t)(n0 + nr) * NFEAT + k0 + c] = __float2half_rn(s[c][nr]);
        }
    } else if (b < 768) {                  // W1/W2 [512x256] -> interleaved Wt12
        int t2 = b - 512;
        int p  = t2 & 1;
        int tile = t2 >> 1;
        int k0 = (tile & 15) * 32;
        int j0 = (tile >> 4) * 32;
        const float* W = p ? W2 : W1;
        #pragma unroll
        for (int rr = 0; rr < 4; rr++)
            s[r + rr * 8][c] = W[(size_t)(k0 + r + rr * 8) * NHID + j0 + c];
        __syncthreads();
        #pragma unroll
        for (int rr = 0; rr < 4; rr++) {
            int jr = r + rr * 8;
            g_Wt12[(size_t)(2 * (j0 + jr) + p) * NCOMP + k0 + c]
                = __float2half_rn(s[c][jr]);
        }
    } else {                               // zero slide_agg accumulator
        for (int i = t; i < 2 * NCOMP; i += 256) g_agg[i] = 0.0f;
    }
}

// ---------------------------------------------------------------------------
// GEMM1: h = relu(x @ Wc + bc).  BM=128, BN=256, K=1024, 512 threads
// (16 warps, 4x4 of 32x64), 3-stage pipeline, SW128 swizzle.
// A: fp32 LDG -> reg convert -> STS (conversion fused).
// Epilogue writes h fp32 (out) + fp16 (g_hh).
// ---------------------------------------------------------------------------
__global__ void __launch_bounds__(512, 1)
gemm1(const float* __restrict__ x, const float* __restrict__ bc,
      float* __restrict__ out)
{
    constexpr int K      = NFEAT;
    constexpr int NT     = K / 64;
    constexpr int ABYTES = 128 * 128;
    constexpr int STRIDE = ABYTES + 256 * 128;      // 48 KB / stage

    extern __shared__ __align__(1024) char smem[];

    const int tid  = threadIdx.x;
    const int lane = tid & 31;
    const int wid  = tid >> 5;
    const int wm   = (wid >> 2) * 32;
    const int wn   = (wid & 3) * 64;
    const int rowBase = blockIdx.y * 128;
    const int colBase = blockIdx.x * 256;

    const uint32_t sbase = smem_u32(smem);

    const int aRowOff = (lane & 7) + ((lane >> 3) & 1) * 8;
    const int aCk     = (lane >> 4) & 1;
    const int bRowOff = (lane & 7) + ((lane >> 4) & 1) * 8;
    const int bCk     = (lane >> 3) & 1;

    float acc[2][8][4];
    #pragma unroll
    for (int mi = 0; mi < 2; mi++)
        #pragma unroll
        for (int ni = 0; ni < 8; ni++)
            #pragma unroll
            for (int q = 0; q < 4; q++) acc[mi][ni][q] = 0.0f;

    auto load_b = [&](int kt, int stg) {
        const uint32_t sB = sbase + stg * STRIDE + ABYTES;
        const __half* Bg = g_Wct + (size_t)colBase * K + kt * 64;
        #pragma unroll
        for (int i = 0; i < 4; i++) {
            int lin = tid + 512 * i;
            int row = lin >> 3, seg = lin & 7;
            uint32_t sa = sB + row * 128 + ((seg ^ (row & 7)) << 4);
            CPASYNC16(sa, Bg + (size_t)row * K + seg * 8);
        }
    };

    float4 areg[4];
    auto ldg_a = [&](int kt) {
        #pragma unroll
        for (int i = 0; i < 2; i++) {
            int lin = tid + 512 * i;
            int row = lin >> 3, seg = lin & 7;
            int gr  = rowBase + row;
            if (gr < M_BAG) {
                const float4* p = reinterpret_cast<const float4*>(
                    x + (size_t)gr * K + kt * 64 + seg * 8);
                areg[2 * i]     = p[0];
                areg[2 * i + 1] = p[1];
            } else {
                areg[2 * i]     = make_float4(0.f, 0.f, 0.f, 0.f);
                areg[2 * i + 1] = make_float4(0.f, 0.f, 0.f, 0.f);
            }
        }
    };
    auto sts_a = [&](int stg) {
        char* sA = smem + stg * STRIDE;
        #pragma unroll
        for (int i = 0; i < 2; i++) {
            int lin = tid + 512 * i;
            int row = lin >> 3, seg = lin & 7;
            float4 a = areg[2 * i], b = areg[2 * i + 1];
            __half2 h0 = __floats2half2_rn(a.x, a.y);
            __half2 h1 = __floats2half2_rn(a.z, a.w);
            __half2 h2 = __floats2half2_rn(b.x, b.y);
            __half2 h3 = __floats2half2_rn(b.z, b.w);
            uint4 v;
            v.x = *reinterpret_cast<uint32_t*>(&h0);
            v.y = *reinterpret_cast<uint32_t*>(&h1);
            v.z = *reinterpret_cast<uint32_t*>(&h2);
            v.w = *reinterpret_cast<uint32_t*>(&h3);
            *reinterpret_cast<uint4*>(sA + row * 128 + ((seg ^ (row & 7)) << 4)) = v;
        }
    };

    ldg_a(0); load_b(0, 0); CPCOMMIT(); sts_a(0);
    ldg_a(1); load_b(1, 1); CPCOMMIT(); sts_a(1);

    for (int kt = 0; kt < NT; kt++) {
        if (kt == NT - 1) cp_wait<0>(); else cp_wait<1>();
        __syncthreads();

        const bool pre = (kt + 2 < NT);
        const int  nstg = (kt + 2) % 3;
        if (pre) {
            ldg_a(kt + 2);
            load_b(kt + 2, nstg);
            CPCOMMIT();
        }

        const uint32_t sA = sbase + (kt % 3) * STRIDE;
        const uint32_t sB = sA + ABYTES;

        #pragma unroll
        for (int ks = 0; ks < 4; ks++) {
            uint32_t a[2][4];
            #pragma unroll
            for (int mi = 0; mi < 2; mi++) {
                int row = wm + mi * 16 + aRowOff;
                uint32_t ad = sA + row * 128 +
                              (((ks * 2 + aCk) ^ (row & 7)) << 4);
                ldsm4(a[mi][0], a[mi][1], a[mi][2], a[mi][3], ad);
            }
            #pragma unroll
            for (int np = 0; np < 4; np++) {
                uint32_t b0, b1r, b2r, b3r;
                int row = wn + np * 16 + bRowOff;
                uint32_t bd = sB + row * 128 +
                              (((ks * 2 + bCk) ^ (row & 7)) << 4);
                ldsm4(b0, b1r, b2r, b3r, bd);
                #pragma unroll
                for (int mi = 0; mi < 2; mi++) {
                    mma16816(acc[mi][2 * np + 0], a[mi], b0, b1r);
                    mma16816(acc[mi][2 * np + 1], a[mi], b2r, b3r);
                }
            }
        }

        if (pre) sts_a(nstg);
    }

    // epilogue: bias + relu, dual store
    const int qrow = lane >> 2;
    const int qcol = (lane & 3) * 2;
    float* h32 = out + OFF_H;
    float2 bias_v[8];
    #pragma unroll
    for (int ni = 0; ni < 8; ni++) {
        int col = colBase + wn + ni * 8 + qcol;
        bias_v[ni] = *reinterpret_cast<const float2*>(bc + col);
    }
    #pragma unroll
    for (int mi = 0; mi < 2; mi++) {
        int r0 = rowBase + wm + mi * 16 + qrow;
        int r1 = r0 + 8;
        #pragma unroll
        for (int ni = 0; ni < 8; ni++) {
            int col = colBase + wn + ni * 8 + qcol;
            float v0 = fmaxf(acc[mi][ni][0] + bias_v[ni].x, 0.f);
            float v1 = fmaxf(acc[mi][ni][1] + bias_v[ni].y, 0.f);
            float v2 = fmaxf(acc[mi][ni][2] + bias_v[ni].x, 0.f);
            float v3 = fmaxf(acc[mi][ni][3] + bias_v[ni].y, 0.f);
            if (r0 < M_BAG) {
                *reinterpret_cast<float2*>(h32 + (size_t)r0 * NCOMP + col)
                    = make_float2(v0, v1);
                __half2 p = __floats2half2_rn(v0, v1);
                *reinterpret_cast<__half2*>(g_hh + (size_t)r0 * NCOMP + col) = p;
            }
            if (r1 < M_BAG) {
                *reinterpret_cast<float2*>(h32 + (size_t)r1 * NCOMP + col)
                    = make_float2(v2, v3);
                __half2 p = __floats2half2_rn(v2, v3);
                *reinterpret_cast<__half2*>(g_hh + (size_t)r1 * NCOMP + col) = p;
            }
        }
    }
}

// ---------------------------------------------------------------------------
// GEMM2: fully fused gated attention. BM=64, BN=512 (full N per CTA),
// K=512, 512 threads (16 warps, 2x8 of 32x64), 3-stage pipeline.
// Epilogue: a = tanh(t1)*sigmoid(t2) (MUFU), att = a@W3 + b3 reduced in
// smem, softmax, writes att_score / A / A_I directly. No global atomics.
// ---------------------------------------------------------------------------
__global__ void __launch_bounds__(512, 1)
gemm2(const float* __restrict__ b1, const float* __restrict__ b2,
      const float* __restrict__ W3, const float* __restrict__ b3,
      const int* __restrict__ sl, float* __restrict__ out)
{
    constexpr int K      = NCOMP;
    constexpr int NT     = K / 64;                  // 8
    constexpr int ABYTES = 64 * 128;                // 8 KB
    constexpr int STRIDE = ABYTES + 512 * 128;      // 72 KB / stage

    extern __shared__ __align__(1024) char smem[];

    const int tid  = threadIdx.x;
    const int lane = tid & 31;
    const int wid  = tid >> 5;
    const int wm   = (wid >> 3) * 32;    // 2 warp rows of 32
    const int wn   = (wid & 7) * 64;     // 8 warp cols of 64
    const int rowBase = blockIdx.x * 64;

    const uint32_t sbase = smem_u32(smem);

    const int aRowOff = (lane & 7) + ((lane >> 3) & 1) * 8;
    const int aCk     = (lane >> 4) & 1;
    const int bRowOff = (lane & 7) + ((lane >> 4) & 1) * 8;
    const int bCk     = (lane >> 3) & 1;

    float acc[2][8][4];
    #pragma unroll
    for (int mi = 0; mi < 2; mi++)
        #pragma unroll
        for (int ni = 0; ni < 8; ni++)
            #pragma unroll
            for (int q = 0; q < 4; q++) acc[mi][ni][q] = 0.0f;

    auto load_b = [&](int kt, int stg) {
        const uint32_t sB = sbase + stg * STRIDE + ABYTES;
        const __half* Bg = g_Wt12 + kt * 64;
        #pragma unroll
        for (int i = 0; i < 8; i++) {            // 512 rows x 8 segs / 512 thr
            int lin = tid + 512 * i;
            int row = lin >> 3, seg = lin & 7;
            uint32_t sa = sB + row * 128 + ((seg ^ (row & 7)) << 4);
            CPASYNC16(sa, Bg + (size_t)row * K + seg * 8);
        }
    };
    auto cp_a = [&](int kt, int stg) {
        const uint32_t sA = sbase + stg * STRIDE;
        const __half* Ag = g_hh + (size_t)rowBase * K + kt * 64;
        int row = tid >> 3, seg = tid & 7;       // 64 rows x 8 segs = 512
        uint32_t sa = sA + row * 128 + ((seg ^ (row & 7)) << 4);
        CPASYNC16(sa, Ag + (size_t)row * K + seg * 8);
    };

    cp_a(0, 0); load_b(0, 0); CPCOMMIT();
    cp_a(1, 1); load_b(1, 1); CPCOMMIT();

    for (int kt = 0; kt < NT; kt++) {
        if (kt == NT - 1) cp_wait<0>(); else cp_wait<1>();
        __syncthreads();

        const bool pre = (kt + 2 < NT);
        const int  nstg = (kt + 2) % 3;
        if (pre) {
            cp_a(kt + 2, nstg);
            load_b(kt + 2, nstg);
            CPCOMMIT();
        }

        const uint32_t sA = sbase + (kt % 3) * STRIDE;
        const uint32_t sB = sA + ABYTES;

        #pragma unroll
        for (int ks = 0; ks < 4; ks++) {
            uint32_t a[2][4];
            #pragma unroll
            for (int mi = 0; mi < 2; mi++) {
                int row = wm + mi * 16 + aRowOff;
                uint32_t ad = sA + row * 128 +
                              (((ks * 2 + aCk) ^ (row & 7)) << 4);
                ldsm4(a[mi][0], a[mi][1], a[mi][2], a[mi][3], ad);
            }
            #pragma unroll
            for (int np = 0; np < 4; np++) {
                uint32_t b0, b1r, b2r, b3r;
                int row = wn + np * 16 + bRowOff;
                uint32_t bd = sB + row * 128 +
                              (((ks * 2 + bCk) ^ (row & 7)) << 4);
                ldsm4(b0, b1r, b2r, b3r, bd);
                #pragma unroll
                for (int mi = 0; mi < 2; mi++) {
                    mma16816(acc[mi][2 * np + 0], a[mi], b0, b1r);
                    mma16816(acc[mi][2 * np + 1], a[mi], b2r, b3r);
                }
            }
        }
    }

    // ---- fused epilogue: gate + a@W3 reduced in smem, softmax, outputs ----
    const int qrow = lane >> 2;
    const int qcol = (lane & 3) * 2;
    float* satt = reinterpret_cast<float*>(smem);   // 64 rows x 2 classes

    __syncthreads();
    if (tid < 128) satt[tid] = 0.0f;
    __syncthreads();

    float b1v[8], b2v[8], w3x[8], w3y[8];
    #pragma unroll
    for (int ni = 0; ni < 8; ni++) {
        int j = (wn + ni * 8 + qcol) >> 1;
        b1v[ni] = b1[j];
        b2v[ni] = b2[j];
        float2 w = reinterpret_cast<const float2*>(W3)[j];
        w3x[ni] = w.x; w3y[ni] = w.y;
    }
    #pragma unroll
    for (int mi = 0; mi < 2; mi++) {
        int lr0 = wm + mi * 16 + qrow;
        int lr1 = lr0 + 8;
        float s00 = 0.f, s01 = 0.f, s10 = 0.f, s11 = 0.f;
        #pragma unroll
        for (int ni = 0; ni < 8; ni++) {
            float t1 = acc[mi][ni][0] + b1v[ni];
            float t2 = acc[mi][ni][1] + b2v[ni];
            float a0 = tanha(t1) * fmaf(tanha(0.5f * t2), 0.5f, 0.5f);
            s00 = fmaf(a0, w3x[ni], s00);
            s01 = fmaf(a0, w3y[ni], s01);
            float u1 = acc[mi][ni][2] + b1v[ni];
            float u2 = acc[mi][ni][3] + b2v[ni];
            float a1 = tanha(u1) * fmaf(tanha(0.5f * u2), 0.5f, 0.5f);
            s10 = fmaf(a1, w3x[ni], s10);
            s11 = fmaf(a1, w3y[ni], s11);
        }
        #pragma unroll
        for (int o = 1; o <= 2; o <<= 1) {
            s00 += __shfl_xor_sync(0xffffffffu, s00, o);
            s01 += __shfl_xor_sync(0xffffffffu, s01, o);
            s10 += __shfl_xor_sync(0xffffffffu, s10, o);
            s11 += __shfl_xor_sync(0xffffffffu, s11, o);
        }
        if ((lane & 3) == 0) {
            atomicAdd(&satt[2 * lr0 + 0], s00);
            atomicAdd(&satt[2 * lr0 + 1], s01);
            atomicAdd(&satt[2 * lr1 + 0], s10);
            atomicAdd(&satt[2 * lr1 + 1], s11);
        }
    }
    __syncthreads();

    if (tid < 64) {
        int r = rowBase + tid;
        if (r < M_BAG) {
            float s0 = satt[2 * tid + 0] + b3[0];
            float s1 = satt[2 * tid + 1] + b3[1];
            out[OFF_ATT + 2 * r + 0] = s0;
            out[OFF_ATT + 2 * r + 1] = s1;
            float m  = fmaxf(s0, s1);
            float e0 = expf(s0 - m), e1 = expf(s1 - m);
            float inv = 1.0f / (e0 + e1);
            float A0 = e0 * inv, A1 = e1 * inv;
            out[OFF_A + 2 * r + 0] = A0;
            out[OFF_A + 2 * r + 1] = A1;
            g_AI[r] = (sl[0] != 0) ? A1 : A0;
        }
    }
}

// ---------------------------------------------------------------------------
// Post: agg (blocks 0..1563, 64 rows each, 8-row unroll for MLP) +
// topk stage1 (blocks 1564..1627).  One launch.
// ---------------------------------------------------------------------------
__global__ __launch_bounds__(256)
void post_kernel(const float* __restrict__ Amat)
{
    int b = blockIdx.x;
    int tid = threadIdx.x;

    if (b < AGG_BLOCKS) {
        // ---- slide_agg = A^T @ h (fp16), 64 rows per block ----
        int r0 = b * 64;
        int r1 = min(r0 + 64, M_BAG);
        float a00 = 0.f, a01 = 0.f, a10 = 0.f, a11 = 0.f;
        const __half2* hv2 = reinterpret_cast<const __half2*>(g_hh);
        const float2* Av2 = reinterpret_cast<const float2*>(Amat);

        int n = r0;
        for (; n + 8 <= r1; n += 8) {
            float2 Ar[8];
            __half2 hr[8];
            #pragma unroll
            for (int u = 0; u < 8; u++) {
                Ar[u] = Av2[n + u];
                hr[u] = hv2[(size_t)(n + u) * 256 + tid];
            }
            #pragma unroll
            for (int u = 0; u < 8; u++) {
                float h0 = __low2float(hr[u]), h1 = __high2float(hr[u]);
                a00 = fmaf(Ar[u].x, h0, a00);
                a01 = fmaf(Ar[u].y, h0, a01);
                a10 = fmaf(Ar[u].x, h1, a10);
                a11 = fmaf(Ar[u].y, h1, a11);
            }
        }
        for (; n < r1; n++) {
            float2 Av = Av2[n];
            __half2 hp = hv2[(size_t)n * 256 + tid];
            float h0 = __low2float(hp), h1 = __high2float(hp);
            a00 = fmaf(Av.x, h0, a00);
            a01 = fmaf(Av.y, h0, a01);
            a10 = fmaf(Av.x, h1, a10);
            a11 = fmaf(Av.y, h1, a11);
        }
        int d0 = tid * 2, d1 = tid * 2 + 1;
        atomicAdd(&g_agg[d0],         a00);
        atomicAdd(&g_agg[NCOMP + d0], a01);
        atomicAdd(&g_agg[d1],         a10);
        atomicAdd(&g_agg[NCOMP + d1], a11);
        return;
    }

    // ---- topk stage 1 ----
    __shared__ float svmax[TK_CHUNK];
    __shared__ float svmin[TK_CHUNK];
    __shared__ float rv[256];
    __shared__ int   ri[256];
    int blk = b - AGG_BLOCKS;
    int base = blk * TK_CHUNK;

    for (int i = tid; i < TK_CHUNK; i += 256) {
        int g = base + i;
        float v = (g < M_BAG) ? g_AI[g] : 0.0f;
        svmax[i] = (g < M_BAG) ? v : -FLT_MAX;
        svmin[i] = (g < M_BAG) ? v :  FLT_MAX;
    }
    __syncthreads();

    for (int pass = 0; pass < 8; pass++) {
        float bv = -FLT_MAX; int bi = 0x7fffffff;
        for (int i = tid; i < TK_CHUNK; i += 256) {
            float v = svmax[i]; int g = base + i;
            if (v > bv || (v == bv && g < bi)) { bv = v; bi = g; }
        }
        rv[tid] = bv; ri[tid] = bi;
        __syncthreads();
        for (int s = 128; s > 0; s >>= 1) {
            if (tid < s) {
                float ov = rv[tid + s]; int oi = ri[tid + s];
                if (ov > rv[tid] || (ov == rv[tid] && oi < ri[tid])) { rv[tid] = ov; ri[tid] = oi; }
            }
            __syncthreads();
        }
        if (tid == 0) {
            g_cmaxv[blk * 8 + pass] = rv[0];
            g_cmaxi[blk * 8 + pass] = ri[0];
            svmax[ri[0] - base] = -FLT_MAX;
        }
        __syncthreads();
    }
    for (int pass = 0; pass < 8; pass++) {
        float bv = FLT_MAX; int bi = 0x7fffffff;
        for (int i = tid; i < TK_CHUNK; i += 256) {
            float v = svmin[i]; int g = base + i;
            if (v < bv || (v == bv && g < bi)) { bv = v; bi = g; }
        }
        rv[tid] = bv; ri[tid] = bi;
        __syncthreads();
        for (int s = 128; s > 0; s >>= 1) {
            if (tid < s) {
                float ov = rv[tid + s]; int oi = ri[tid + s];
                if (ov < rv[tid] || (ov == rv[tid] && oi < ri[tid])) { rv[tid] = ov; ri[tid] = oi; }
            }
            __syncthreads();
        }
        if (tid == 0) {
            g_cminv[blk * 8 + pass] = rv[0];
            g_cmini[blk * 8 + pass] = ri[0];
            svmin[ri[0] - base] = FLT_MAX;
        }
        __syncthreads();
    }
}

// ---------------------------------------------------------------------------
// topk_final: register-resident warp-shuffle selection (2 barriers/pass)
// + instance head + slide score.  512 threads.
// ---------------------------------------------------------------------------
__global__ __launch_bounds__(512)
void topk_final(const float* __restrict__ W_ins, const float* __restrict__ b_ins,
                const float* __restrict__ W_bag, const float* __restrict__ b_bag,
                const float* __restrict__ h, float* __restrict__ out)
{
    __shared__ float wv[16];
    __shared__ int   wi[16];
    __shared__ int   swin;
    __shared__ int   tix[16];
    __shared__ float s_logit[32];
    __shared__ float s_slide[2];
    int tid  = threadIdx.x;
    int lane = tid & 31;
    int w    = tid >> 5;

    // ---- top-8: each thread owns one candidate in registers ----
    {
        float mv = g_cmaxv[tid];
        int   mi = g_cmaxi[tid];
        #pragma unroll 1
        for (int pass = 0; pass < 8; pass++) {
            float v = mv; int idx = mi;
            #pragma unroll
            for (int o = 16; o > 0; o >>= 1) {
                float ov = __shfl_xor_sync(0xffffffffu, v, o);
                int   oi = __shfl_xor_sync(0xffffffffu, idx, o);
                if (ov > v || (ov == v && oi < idx)) { v = ov; idx = oi; }
            }
            if (lane == 0) { wv[w] = v; wi[w] = idx; }
            __syncthreads();
            if (tid < 16) {
                float v2 = wv[tid]; int i2 = wi[tid];
                #pragma unroll
                for (int o = 8; o > 0; o >>= 1) {
                    float ov = __shfl_xor_sync(0xffffu, v2, o);
                    int   oi = __shfl_xor_sync(0xffffu, i2, o);
                    if (ov > v2 || (ov == v2 && oi < i2)) { v2 = ov; i2 = oi; }
                }
                if (tid == 0) { swin = i2; tix[pass] = i2; }
            }
            __syncthreads();
            if (mi == swin) { mv = -FLT_MAX; mi = 0x7fffffff; }
        }
    }
    // ---- bottom-8 ----
    {
        float mv = g_cminv[tid];
        int   mi = g_cmini[tid];
        #pragma unroll 1
        for (int pass = 0; pass < 8; pass++) {
            float v = mv; int idx = mi;
            #pragma unroll
            for (int o = 16; o > 0; o >>= 1) {
                float ov = __shfl_xor_sync(0xffffffffu, v, o);
                int   oi = __shfl_xor_sync(0xffffffffu, idx, o);
                if (ov < v || (ov == v && oi < idx)) { v = ov; idx = oi; }
            }
            if (lane == 0) { wv[w] = v; wi[w] = idx; }
            __syncthreads();
            if (tid < 16) {
                float v2 = wv[tid]; int i2 = wi[tid];
                #pragma unroll
                for (int o = 8; o > 0; o >>= 1) {
                    float ov = __shfl_xor_sync(0xffffu, v2, o);
                    int   oi = __shfl_xor_sync(0xffffu, i2, o);
                    if (ov < v2 || (ov == v2 && oi < i2)) { v2 = ov; i2 = oi; }
                }
                if (tid == 0) { swin = i2; tix[8 + pass] = i2; }
            }
            __syncthreads();
            if (mi == swin) { mv = FLT_MAX; mi = 0x7fffffff; }
        }
    }

    // ---- instance head: warp w -> row w (both classes) ----
    {
        int idx = tix[w];
        const float* hr = h + (size_t)idx * NCOMP;
        float a0 = 0.f, a1 = 0.f;
        for (int d = lane; d < NCOMP; d += 32) {
            float hv = hr[d];
            a0 = fmaf(hv, W_ins[2 * d + 0], a0);
            a1 = fmaf(hv, W_ins[2 * d + 1], a1);
        }
        #pragma unroll
        for (int o = 16; o > 0; o >>= 1) {
            a0 += __shfl_xor_sync(0xffffffffu, a0, o);
            a1 += __shfl_xor_sync(0xffffffffu, a1, o);
        }
        if (lane == 0) {
            s_logit[w * 2 + 0] = a0 + b_ins[0];
            s_logit[w * 2 + 1] = a1 + b_ins[1];
        }
    }
    if (w < 2) {
        int c = w;
        float acc = 0.f;
        for (int d = lane; d < NCOMP; d += 32)
            acc = fmaf(g_agg[c * NCOMP + d], W_bag[d], acc);
        #pragma unroll
        for (int o = 16; o > 0; o >>= 1)
            acc += __shfl_xor_sync(0xffffffffu, acc, o);
        if (lane == 0) s_slide[c] = acc + b_bag[0];
    }
    __syncthreads();

    if (tid < 16) {
        float l0 = s_logit[tid * 2 + 0];
        float l1 = s_logit[tid * 2 + 1];
        out[OFF_IU + tid * 2 + 0] = l0;
        out[OFF_IU + tid * 2 + 1] = l1;
        float m = fmaxf(l0, l1);
        float e0 = expf(l0 - m), e1 = expf(l1 - m);
        float inv = 1.0f / (e0 + e1);
        out[OFF_IL + tid * 2 + 0] = e0 * inv;
        out[OFF_IL + tid * 2 + 1] = e1 * inv;
        out[OFF_LAB + tid] = (tid < 8) ? 1.0f : 0.0f;
    }
    if (tid == 0) {
        float s0 = s_slide[0], s1 = s_slide[1];
        out[OFF_SS + 0] = s0;
        out[OFF_SS + 1] = s1;
        float m = fmaxf(s0, s1);
        float e0 = expf(s0 - m), e1 = expf(s1 - m);
        float inv = 1.0f / (e0 + e1);
        out[OFF_YP + 0] = e0 * inv;
        out[OFF_YP + 1] = e1 * inv;
        out[OFF_YH] = (s1 > s0) ? 1.0f : 0.0f;
    }
}

// ---------------------------------------------------------------------------
// kernel_launch
// ---------------------------------------------------------------------------
extern "C" void kernel_launch(void* const* d_in, const int* in_sizes, int n_in,
                              void* d_out, int out_size)
{
    const float* x   = (const float*)d_in[0];
    const int*   sl  = (const int*)  d_in[1];
    const float* Wc  = (const float*)d_in[2];
    const float* bc  = (const float*)d_in[3];
    const float* W1  = (const float*)d_in[4];
    const float* b1  = (const float*)d_in[5];
    const float* W2  = (const float*)d_in[6];
    const float* b2  = (const float*)d_in[7];
    const float* W3  = (const float*)d_in[8];
    const float* b3  = (const float*)d_in[9];
    const float* Wi  = (const float*)d_in[10];
    const float* bi  = (const float*)d_in[11];
    const float* Wb  = (const float*)d_in[12];
    const float* bb  = (const float*)d_in[13];

    float* out = (float*)d_out;
    float* h   = out + OFF_H;

    const int SMEM1 = 3 * (128 * 128 + 256 * 128);  // 144 KB
    const int SMEM2 = 3 * (64 * 128 + 512 * 128);   // 216 KB
    cudaFuncSetAttribute(gemm1, cudaFuncAttributeMaxDynamicSharedMemorySize, SMEM1);
    cudaFuncSetAttribute(gemm2, cudaFuncAttributeMaxDynamicSharedMemorySize, SMEM2);

    prep_kernel<<<769, 256>>>(Wc, W1, W2);

    // h = relu(x @ Wc + bc)
    gemm1<<<dim3(2, M_PAD / 128), 512, SMEM1>>>(x, bc, out);

    // gated attention GEMM, fully fused softmax epilogue
    gemm2<<<M_PAD / 64, 512, SMEM2>>>(b1, b2, W3, b3, sl, out);

    // slide_agg (high-parallelism) + topk stage 1, one launch
    post_kernel<<<AGG_BLOCKS + TK_BLOCKS, 256>>>(out + OFF_A);

    // register/shuffle topk stage2 + instance head + slide score
    topk_final<<<1, 512>>>(Wi, bi, Wb, bb, h, out);
}

// round 14
// speedup vs baseline: 1.0318x; 1.0318x over previous
#include <cuda_runtime.h>
#include <cuda_fp16.h>
#include <math.h>
#include <float.h>
#include <stdint.h>

// ---------------------------------------------------------------------------
// Problem constants
// ---------------------------------------------------------------------------
#define M_BAG   100000
#define M_PAD   100096          // 782 * 128 = 1564 * 64
#define NFEAT   1024
#define NCOMP   512
#define NHID    256

// Output layout (flattened reference tuple, fp32)
#define OFF_ATT   0u
#define OFF_A     200000u
#define OFF_H     400000u
#define OFF_LAB   51600000u
#define OFF_IU    51600016u
#define OFF_IL    51600048u
#define OFF_SS    51600080u
#define OFF_YP    51600082u
#define OFF_YH    51600084u

// ---------------------------------------------------------------------------
// Device scratch (static globals; allocation-free per harness rules)
// ---------------------------------------------------------------------------
__device__ __half g_hh[(size_t)M_PAD * NCOMP];    // h in fp16 (padded rows zero)
__device__ __half g_Wct[(size_t)NCOMP * NFEAT];   // Wc^T  [512][1024]
__device__ __half g_Wt12[(size_t)NCOMP * NCOMP];  // interleaved [W1|W2]^T [512][512]
__device__ float  g_AI[M_BAG];
__device__ float  g_agg[2 * NCOMP];
#define TK_BLOCKS 64
#define TK_CHUNK  1568
#define AGG_BLOCKS 391
__device__ float  g_cmaxv[TK_BLOCKS * 8];
__device__ int    g_cmaxi[TK_BLOCKS * 8];
__device__ float  g_cminv[TK_BLOCKS * 8];
__device__ int    g_cmini[TK_BLOCKS * 8];

// ---------------------------------------------------------------------------
// PTX helpers (sm_80+ features only: mma.sync / ldmatrix / cp.async)
// ---------------------------------------------------------------------------
__device__ __forceinline__ uint32_t smem_u32(const void* p) {
    uint32_t a;
    asm("{ .reg .u64 t; cvta.to.shared.u64 t, %1; cvt.u32.u64 %0, t; }"
        : "=r"(a) : "l"(p));
    return a;
}

#define CPASYNC16(sa, gp) \
    asm volatile("cp.async.cg.shared.global [%0], [%1], 16;" \
                 :: "r"(sa), "l"(gp))
#define CPCOMMIT() asm volatile("cp.async.commit_group;")
template<int N> __device__ __forceinline__ void cp_wait() {
    asm volatile("cp.async.wait_group %0;" :: "n"(N));
}

__device__ __forceinline__ void ldsm4(uint32_t& r0, uint32_t& r1,
                                      uint32_t& r2, uint32_t& r3, uint32_t a) {
    asm volatile("ldmatrix.sync.aligned.m8n8.x4.shared.b16 {%0,%1,%2,%3}, [%4];"
                 : "=r"(r0), "=r"(r1), "=r"(r2), "=r"(r3) : "r"(a));
}

__device__ __forceinline__ void mma16816(float* c, const uint32_t* a,
                                         uint32_t b0, uint32_t b1) {
    asm volatile(
        "mma.sync.aligned.m16n8k16.row.col.f32.f16.f16.f32 "
        "{%0,%1,%2,%3}, {%4,%5,%6,%7}, {%8,%9}, {%0,%1,%2,%3};"
        : "+f"(c[0]), "+f"(c[1]), "+f"(c[2]), "+f"(c[3])
        : "r"(a[0]), "r"(a[1]), "r"(a[2]), "r"(a[3]), "r"(b0), "r"(b1));
}

__device__ __forceinline__ float tanha(float x) {
    float y; asm("tanh.approx.f32 %0, %1;" : "=f"(y) : "f"(x)); return y;
}

// ---------------------------------------------------------------------------
// Prep: coalesced tiled transposes (Wc^T, interleaved [W1|W2]^T) + zero g_agg
// grid = 769 blocks x 256 threads
// ---------------------------------------------------------------------------
__global__ __launch_bounds__(256)
void prep_kernel(const float* __restrict__ Wc,
                 const float* __restrict__ W1,
                 const float* __restrict__ W2)
{
    __shared__ float s[32][33];
    int b = blockIdx.x;
    int t = threadIdx.x;
    int r = t >> 5, c = t & 31;

    if (b < 512) {                         // Wc [1024x512] -> Wct [512][1024]
        int k0 = (b & 31) * 32;
        int n0 = (b >> 5) * 32;
        #pragma unroll
        for (int rr = 0; rr < 4; rr++)
            s[r + rr * 8][c] = Wc[(size_t)(k0 + r + rr * 8) * NCOMP + n0 + c];
        __syncthreads();
        #pragma unroll
        for (int rr = 0; rr < 4; rr++) {
            int nr = r + rr * 8;
            g_Wct[(size_t)(n0 + nr) * NFEAT + k0 + c] = __float2half_rn(s[c][nr]);
        }
    } else if (b < 768) {                  // W1/W2 [512x256] -> interleaved Wt12
        int t2 = b - 512;
        int p  = t2 & 1;
        int tile = t2 >> 1;
        int k0 = (tile & 15) * 32;
        int j0 = (tile >> 4) * 32;
        const float* W = p ? W2 : W1;
        #pragma unroll
        for (int rr = 0; rr < 4; rr++)
            s[r + rr * 8][c] = W[(size_t)(k0 + r + rr * 8) * NHID + j0 + c];
        __syncthreads();
        #pragma unroll
        for (int rr = 0; rr < 4; rr++) {
            int jr = r + rr * 8;
            g_Wt12[(size_t)(2 * (j0 + jr) + p) * NCOMP + k0 + c]
                = __float2half_rn(s[c][jr]);
        }
    } else {                               // zero slide_agg accumulator
        for (int i = t; i < 2 * NCOMP; i += 256) g_agg[i] = 0.0f;
    }
}

// ---------------------------------------------------------------------------
// GEMM1: h = relu(x @ Wc + bc).  BM=128, BN=256, K=1024, 512 threads
// (16 warps, 4x4 of 32x64), 3-stage pipeline, SW128 swizzle.
// A: fp32 LDG -> reg convert -> STS (conversion fused).
// Epilogue writes h fp32 (out) + fp16 (g_hh).
// ---------------------------------------------------------------------------
__global__ void __launch_bounds__(512, 1)
gemm1(const float* __restrict__ x, const float* __restrict__ bc,
      float* __restrict__ out)
{
    constexpr int K      = NFEAT;
    constexpr int NT     = K / 64;
    constexpr int ABYTES = 128 * 128;
    constexpr int STRIDE = ABYTES + 256 * 128;      // 48 KB / stage

    extern __shared__ __align__(1024) char smem[];

    const int tid  = threadIdx.x;
    const int lane = tid & 31;
    const int wid  = tid >> 5;
    const int wm   = (wid >> 2) * 32;
    const int wn   = (wid & 3) * 64;
    const int rowBase = blockIdx.y * 128;
    const int colBase = blockIdx.x * 256;

    const uint32_t sbase = smem_u32(smem);

    const int aRowOff = (lane & 7) + ((lane >> 3) & 1) * 8;
    const int aCk     = (lane >> 4) & 1;
    const int bRowOff = (lane & 7) + ((lane >> 4) & 1) * 8;
    const int bCk     = (lane >> 3) & 1;

    float acc[2][8][4];
    #pragma unroll
    for (int mi = 0; mi < 2; mi++)
        #pragma unroll
        for (int ni = 0; ni < 8; ni++)
            #pragma unroll
            for (int q = 0; q < 4; q++) acc[mi][ni][q] = 0.0f;

    auto load_b = [&](int kt, int stg) {
        const uint32_t sB = sbase + stg * STRIDE + ABYTES;
        const __half* Bg = g_Wct + (size_t)colBase * K + kt * 64;
        #pragma unroll
        for (int i = 0; i < 4; i++) {
            int lin = tid + 512 * i;
            int row = lin >> 3, seg = lin & 7;
            uint32_t sa = sB + row * 128 + ((seg ^ (row & 7)) << 4);
            CPASYNC16(sa, Bg + (size_t)row * K + seg * 8);
        }
    };

    float4 areg[4];
    auto ldg_a = [&](int kt) {
        #pragma unroll
        for (int i = 0; i < 2; i++) {
            int lin = tid + 512 * i;
            int row = lin >> 3, seg = lin & 7;
            int gr  = rowBase + row;
            if (gr < M_BAG) {
                const float4* p = reinterpret_cast<const float4*>(
                    x + (size_t)gr * K + kt * 64 + seg * 8);
                areg[2 * i]     = p[0];
                areg[2 * i + 1] = p[1];
            } else {
                areg[2 * i]     = make_float4(0.f, 0.f, 0.f, 0.f);
                areg[2 * i + 1] = make_float4(0.f, 0.f, 0.f, 0.f);
            }
        }
    };
    auto sts_a = [&](int stg) {
        char* sA = smem + stg * STRIDE;
        #pragma unroll
        for (int i = 0; i < 2; i++) {
            int lin = tid + 512 * i;
            int row = lin >> 3, seg = lin & 7;
            float4 a = areg[2 * i], b = areg[2 * i + 1];
            __half2 h0 = __floats2half2_rn(a.x, a.y);
            __half2 h1 = __floats2half2_rn(a.z, a.w);
            __half2 h2 = __floats2half2_rn(b.x, b.y);
            __half2 h3 = __floats2half2_rn(b.z, b.w);
            uint4 v;
            v.x = *reinterpret_cast<uint32_t*>(&h0);
            v.y = *reinterpret_cast<uint32_t*>(&h1);
            v.z = *reinterpret_cast<uint32_t*>(&h2);
            v.w = *reinterpret_cast<uint32_t*>(&h3);
            *reinterpret_cast<uint4*>(sA + row * 128 + ((seg ^ (row & 7)) << 4)) = v;
        }
    };

    ldg_a(0); load_b(0, 0); CPCOMMIT(); sts_a(0);
    ldg_a(1); load_b(1, 1); CPCOMMIT(); sts_a(1);

    for (int kt = 0; kt < NT; kt++) {
        if (kt == NT - 1) cp_wait<0>(); else cp_wait<1>();
        __syncthreads();

        const bool pre = (kt + 2 < NT);
        const int  nstg = (kt + 2) % 3;
        if (pre) {
            ldg_a(kt + 2);
            load_b(kt + 2, nstg);
            CPCOMMIT();
        }

        const uint32_t sA = sbase + (kt % 3) * STRIDE;
        const uint32_t sB = sA + ABYTES;

        #pragma unroll
        for (int ks = 0; ks < 4; ks++) {
            uint32_t a[2][4];
            #pragma unroll
            for (int mi = 0; mi < 2; mi++) {
                int row = wm + mi * 16 + aRowOff;
                uint32_t ad = sA + row * 128 +
                              (((ks * 2 + aCk) ^ (row & 7)) << 4);
                ldsm4(a[mi][0], a[mi][1], a[mi][2], a[mi][3], ad);
            }
            #pragma unroll
            for (int np = 0; np < 4; np++) {
                uint32_t b0, b1r, b2r, b3r;
                int row = wn + np * 16 + bRowOff;
                uint32_t bd = sB + row * 128 +
                              (((ks * 2 + bCk) ^ (row & 7)) << 4);
                ldsm4(b0, b1r, b2r, b3r, bd);
                #pragma unroll
                for (int mi = 0; mi < 2; mi++) {
                    mma16816(acc[mi][2 * np + 0], a[mi], b0, b1r);
                    mma16816(acc[mi][2 * np + 1], a[mi], b2r, b3r);
                }
            }
        }

        if (pre) sts_a(nstg);
    }

    // epilogue: bias + relu, dual store
    const int qrow = lane >> 2;
    const int qcol = (lane & 3) * 2;
    float* h32 = out + OFF_H;
    float2 bias_v[8];
    #pragma unroll
    for (int ni = 0; ni < 8; ni++) {
        int col = colBase + wn + ni * 8 + qcol;
        bias_v[ni] = *reinterpret_cast<const float2*>(bc + col);
    }
    #pragma unroll
    for (int mi = 0; mi < 2; mi++) {
        int r0 = rowBase + wm + mi * 16 + qrow;
        int r1 = r0 + 8;
        #pragma unroll
        for (int ni = 0; ni < 8; ni++) {
            int col = colBase + wn + ni * 8 + qcol;
            float v0 = fmaxf(acc[mi][ni][0] + bias_v[ni].x, 0.f);
            float v1 = fmaxf(acc[mi][ni][1] + bias_v[ni].y, 0.f);
            float v2 = fmaxf(acc[mi][ni][2] + bias_v[ni].x, 0.f);
            float v3 = fmaxf(acc[mi][ni][3] + bias_v[ni].y, 0.f);
            if (r0 < M_BAG) {
                *reinterpret_cast<float2*>(h32 + (size_t)r0 * NCOMP + col)
                    = make_float2(v0, v1);
                __half2 p = __floats2half2_rn(v0, v1);
                *reinterpret_cast<__half2*>(g_hh + (size_t)r0 * NCOMP + col) = p;
            }
            if (r1 < M_BAG) {
                *reinterpret_cast<float2*>(h32 + (size_t)r1 * NCOMP + col)
                    = make_float2(v2, v3);
                __half2 p = __floats2half2_rn(v2, v3);
                *reinterpret_cast<__half2*>(g_hh + (size_t)r1 * NCOMP + col) = p;
            }
        }
    }
}

// ---------------------------------------------------------------------------
// GEMM2: fully fused gated attention. BM=64, BN=512 (full N per CTA),
// K=512, 512 threads (16 warps, 2x8 of 32x64), 3-stage pipeline.
// Epilogue: a = tanh(t1)*sigmoid(t2) (MUFU), att = a@W3 + b3 reduced in
// smem, softmax, writes att_score / A / A_I directly. No global atomics.
// ---------------------------------------------------------------------------
__global__ void __launch_bounds__(512, 1)
gemm2(const float* __restrict__ b1, const float* __restrict__ b2,
      const float* __restrict__ W3, const float* __restrict__ b3,
      const int* __restrict__ sl, float* __restrict__ out)
{
    constexpr int K      = NCOMP;
    constexpr int NT     = K / 64;                  // 8
    constexpr int ABYTES = 64 * 128;                // 8 KB
    constexpr int STRIDE = ABYTES + 512 * 128;      // 72 KB / stage

    extern __shared__ __align__(1024) char smem[];

    const int tid  = threadIdx.x;
    const int lane = tid & 31;
    const int wid  = tid >> 5;
    const int wm   = (wid >> 3) * 32;    // 2 warp rows of 32
    const int wn   = (wid & 7) * 64;     // 8 warp cols of 64
    const int rowBase = blockIdx.x * 64;

    const uint32_t sbase = smem_u32(smem);

    const int aRowOff = (lane & 7) + ((lane >> 3) & 1) * 8;
    const int aCk     = (lane >> 4) & 1;
    const int bRowOff = (lane & 7) + ((lane >> 4) & 1) * 8;
    const int bCk     = (lane >> 3) & 1;

    float acc[2][8][4];
    #pragma unroll
    for (int mi = 0; mi < 2; mi++)
        #pragma unroll
        for (int ni = 0; ni < 8; ni++)
            #pragma unroll
            for (int q = 0; q < 4; q++) acc[mi][ni][q] = 0.0f;

    auto load_b = [&](int kt, int stg) {
        const uint32_t sB = sbase + stg * STRIDE + ABYTES;
        const __half* Bg = g_Wt12 + kt * 64;
        #pragma unroll
        for (int i = 0; i < 8; i++) {            // 512 rows x 8 segs / 512 thr
            int lin = tid + 512 * i;
            int row = lin >> 3, seg = lin & 7;
            uint32_t sa = sB + row * 128 + ((seg ^ (row & 7)) << 4);
            CPASYNC16(sa, Bg + (size_t)row * K + seg * 8);
        }
    };
    auto cp_a = [&](int kt, int stg) {
        const uint32_t sA = sbase + stg * STRIDE;
        const __half* Ag = g_hh + (size_t)rowBase * K + kt * 64;
        int row = tid >> 3, seg = tid & 7;       // 64 rows x 8 segs = 512
        uint32_t sa = sA + row * 128 + ((seg ^ (row & 7)) << 4);
        CPASYNC16(sa, Ag + (size_t)row * K + seg * 8);
    };

    cp_a(0, 0); load_b(0, 0); CPCOMMIT();
    cp_a(1, 1); load_b(1, 1); CPCOMMIT();

    for (int kt = 0; kt < NT; kt++) {
        if (kt == NT - 1) cp_wait<0>(); else cp_wait<1>();
        __syncthreads();

        const bool pre = (kt + 2 < NT);
        const int  nstg = (kt + 2) % 3;
        if (pre) {
            cp_a(kt + 2, nstg);
            load_b(kt + 2, nstg);
            CPCOMMIT();
        }

        const uint32_t sA = sbase + (kt % 3) * STRIDE;
        const uint32_t sB = sA + ABYTES;

        #pragma unroll
        for (int ks = 0; ks < 4; ks++) {
            uint32_t a[2][4];
            #pragma unroll
            for (int mi = 0; mi < 2; mi++) {
                int row = wm + mi * 16 + aRowOff;
                uint32_t ad = sA + row * 128 +
                              (((ks * 2 + aCk) ^ (row & 7)) << 4);
                ldsm4(a[mi][0], a[mi][1], a[mi][2], a[mi][3], ad);
            }
            #pragma unroll
            for (int np = 0; np < 4; np++) {
                uint32_t b0, b1r, b2r, b3r;
                int row = wn + np * 16 + bRowOff;
                uint32_t bd = sB + row * 128 +
                              (((ks * 2 + bCk) ^ (row & 7)) << 4);
                ldsm4(b0, b1r, b2r, b3r, bd);
                #pragma unroll
                for (int mi = 0; mi < 2; mi++) {
                    mma16816(acc[mi][2 * np + 0], a[mi], b0, b1r);
                    mma16816(acc[mi][2 * np + 1], a[mi], b2r, b3r);
                }
            }
        }
    }

    // ---- fused epilogue: gate + a@W3 reduced in smem, softmax, outputs ----
    const int qrow = lane >> 2;
    const int qcol = (lane & 3) * 2;
    float* satt = reinterpret_cast<float*>(smem);   // 64 rows x 2 classes

    __syncthreads();
    if (tid < 128) satt[tid] = 0.0f;
    __syncthreads();

    float b1v[8], b2v[8], w3x[8], w3y[8];
    #pragma unroll
    for (int ni = 0; ni < 8; ni++) {
        int j = (wn + ni * 8 + qcol) >> 1;
        b1v[ni] = b1[j];
        b2v[ni] = b2[j];
        float2 w = reinterpret_cast<const float2*>(W3)[j];
        w3x[ni] = w.x; w3y[ni] = w.y;
    }
    #pragma unroll
    for (int mi = 0; mi < 2; mi++) {
        int lr0 = wm + mi * 16 + qrow;
        int lr1 = lr0 + 8;
        float s00 = 0.f, s01 = 0.f, s10 = 0.f, s11 = 0.f;
        #pragma unroll
        for (int ni = 0; ni < 8; ni++) {
            float t1 = acc[mi][ni][0] + b1v[ni];
            float t2 = acc[mi][ni][1] + b2v[ni];
            float a0 = tanha(t1) * fmaf(tanha(0.5f * t2), 0.5f, 0.5f);
            s00 = fmaf(a0, w3x[ni], s00);
            s01 = fmaf(a0, w3y[ni], s01);
            float u1 = acc[mi][ni][2] + b1v[ni];
            float u2 = acc[mi][ni][3] + b2v[ni];
            float a1 = tanha(u1) * fmaf(tanha(0.5f * u2), 0.5f, 0.5f);
            s10 = fmaf(a1, w3x[ni], s10);
            s11 = fmaf(a1, w3y[ni], s11);
        }
        #pragma unroll
        for (int o = 1; o <= 2; o <<= 1) {
            s00 += __shfl_xor_sync(0xffffffffu, s00, o);
            s01 += __shfl_xor_sync(0xffffffffu, s01, o);
            s10 += __shfl_xor_sync(0xffffffffu, s10, o);
            s11 += __shfl_xor_sync(0xffffffffu, s11, o);
        }
        if ((lane & 3) == 0) {
            atomicAdd(&satt[2 * lr0 + 0], s00);
            atomicAdd(&satt[2 * lr0 + 1], s01);
            atomicAdd(&satt[2 * lr1 + 0], s10);
            atomicAdd(&satt[2 * lr1 + 1], s11);
        }
    }
    __syncthreads();

    if (tid < 64) {
        int r = rowBase + tid;
        if (r < M_BAG) {
            float s0 = satt[2 * tid + 0] + b3[0];
            float s1 = satt[2 * tid + 1] + b3[1];
            out[OFF_ATT + 2 * r + 0] = s0;
            out[OFF_ATT + 2 * r + 1] = s1;
            float m  = fmaxf(s0, s1);
            float e0 = expf(s0 - m), e1 = expf(s1 - m);
            float inv = 1.0f / (e0 + e1);
            float A0 = e0 * inv, A1 = e1 * inv;
            out[OFF_A + 2 * r + 0] = A0;
            out[OFF_A + 2 * r + 1] = A1;
            g_AI[r] = (sl[0] != 0) ? A1 : A0;
        }
    }
}

// ---------------------------------------------------------------------------
// Post: agg (blocks 0..390, 256 rows, vectorized uint4 loads + smem
// pre-reduction) + topk stage1 (blocks 391..454).  One launch.
// ---------------------------------------------------------------------------
__global__ __launch_bounds__(256)
void post_kernel(const float* __restrict__ Amat)
{
    int b = blockIdx.x;
    int tid = threadIdx.x;

    if (b < AGG_BLOCKS) {
        // ---- slide_agg = A^T @ h (fp16) ----
        // thread: cg = tid & 63 -> 8 columns [cg*8, cg*8+8); ro = tid >> 6
        __shared__ float sred[2 * NCOMP];      // 4 KB
        const int cg = tid & 63;
        const int ro = tid >> 6;
        int r0 = b * 256;
        int r1 = min(r0 + 256, M_BAG);

        float c0[8], c1[8];
        #pragma unroll
        for (int k = 0; k < 8; k++) { c0[k] = 0.f; c1[k] = 0.f; }

        const float2* Av2 = reinterpret_cast<const float2*>(Amat);
        #pragma unroll 2
        for (int n = r0 + ro; n < r1; n += 4) {
            float2 Av = Av2[n];
            uint4 hv = *reinterpret_cast<const uint4*>(
                g_hh + (size_t)n * NCOMP + cg * 8);
            __half2 p0 = *reinterpret_cast<__half2*>(&hv.x);
            __half2 p1 = *reinterpret_cast<__half2*>(&hv.y);
            __half2 p2 = *reinterpret_cast<__half2*>(&hv.z);
            __half2 p3 = *reinterpret_cast<__half2*>(&hv.w);
            float f[8];
            f[0] = __low2float(p0); f[1] = __high2float(p0);
            f[2] = __low2float(p1); f[3] = __high2float(p1);
            f[4] = __low2float(p2); f[5] = __high2float(p2);
            f[6] = __low2float(p3); f[7] = __high2float(p3);
            #pragma unroll
            for (int k = 0; k < 8; k++) {
                c0[k] = fmaf(Av.x, f[k], c0[k]);
                c1[k] = fmaf(Av.y, f[k], c1[k]);
            }
        }

        // smem pre-reduction (<=4-way contention per address)
        for (int i = tid; i < 2 * NCOMP; i += 256) sred[i] = 0.0f;
        __syncthreads();
        #pragma unroll
        for (int k = 0; k < 8; k++) {
            atomicAdd(&sred[cg * 8 + k],         c0[k]);
            atomicAdd(&sred[NCOMP + cg * 8 + k], c1[k]);
        }
        __syncthreads();
        #pragma unroll
        for (int i = 0; i < 4; i++) {
            int idx = tid * 4 + i;
            atomicAdd(&g_agg[idx], sred[idx]);
        }
        return;
    }

    // ---- topk stage 1 ----
    __shared__ float svmax[TK_CHUNK];
    __shared__ float svmin[TK_CHUNK];
    __shared__ float rv[256];
    __shared__ int   ri[256];
    int blk = b - AGG_BLOCKS;
    int base = blk * TK_CHUNK;

    for (int i = tid; i < TK_CHUNK; i += 256) {
        int g = base + i;
        float v = (g < M_BAG) ? g_AI[g] : 0.0f;
        svmax[i] = (g < M_BAG) ? v : -FLT_MAX;
        svmin[i] = (g < M_BAG) ? v :  FLT_MAX;
    }
    __syncthreads();

    for (int pass = 0; pass < 8; pass++) {
        float bv = -FLT_MAX; int bi = 0x7fffffff;
        for (int i = tid; i < TK_CHUNK; i += 256) {
            float v = svmax[i]; int g = base + i;
            if (v > bv || (v == bv && g < bi)) { bv = v; bi = g; }
        }
        rv[tid] = bv; ri[tid] = bi;
        __syncthreads();
        for (int s = 128; s > 0; s >>= 1) {
            if (tid < s) {
                float ov = rv[tid + s]; int oi = ri[tid + s];
                if (ov > rv[tid] || (ov == rv[tid] && oi < ri[tid])) { rv[tid] = ov; ri[tid] = oi; }
            }
            __syncthreads();
        }
        if (tid == 0) {
            g_cmaxv[blk * 8 + pass] = rv[0];
            g_cmaxi[blk * 8 + pass] = ri[0];
            svmax[ri[0] - base] = -FLT_MAX;
        }
        __syncthreads();
    }
    for (int pass = 0; pass < 8; pass++) {
        float bv = FLT_MAX; int bi = 0x7fffffff;
        for (int i = tid; i < TK_CHUNK; i += 256) {
            float v = svmin[i]; int g = base + i;
            if (v < bv || (v == bv && g < bi)) { bv = v; bi = g; }
        }
        rv[tid] = bv; ri[tid] = bi;
        __syncthreads();
        for (int s = 128; s > 0; s >>= 1) {
            if (tid < s) {
                float ov = rv[tid + s]; int oi = ri[tid + s];
                if (ov < rv[tid] || (ov == rv[tid] && oi < ri[tid])) { rv[tid] = ov; ri[tid] = oi; }
            }
            __syncthreads();
        }
        if (tid == 0) {
            g_cminv[blk * 8 + pass] = rv[0];
            g_cmini[blk * 8 + pass] = ri[0];
            svmin[ri[0] - base] = FLT_MAX;
        }
        __syncthreads();
    }
}

// ---------------------------------------------------------------------------
// topk_final: register-resident warp-shuffle selection (2 barriers/pass)
// + instance head + slide score.  512 threads.
// ---------------------------------------------------------------------------
__global__ __launch_bounds__(512)
void topk_final(const float* __restrict__ W_ins, const float* __restrict__ b_ins,
                const float* __restrict__ W_bag, const float* __restrict__ b_bag,
                const float* __restrict__ h, float* __restrict__ out)
{
    __shared__ float wv[16];
    __shared__ int   wi[16];
    __shared__ int   swin;
    __shared__ int   tix[16];
    __shared__ float s_logit[32];
    __shared__ float s_slide[2];
    int tid  = threadIdx.x;
    int lane = tid & 31;
    int w    = tid >> 5;

    // ---- top-8: each thread owns one candidate in registers ----
    {
        float mv = g_cmaxv[tid];
        int   mi = g_cmaxi[tid];
        #pragma unroll 1
        for (int pass = 0; pass < 8; pass++) {
            float v = mv; int idx = mi;
            #pragma unroll
            for (int o = 16; o > 0; o >>= 1) {
                float ov = __shfl_xor_sync(0xffffffffu, v, o);
                int   oi = __shfl_xor_sync(0xffffffffu, idx, o);
                if (ov > v || (ov == v && oi < idx)) { v = ov; idx = oi; }
            }
            if (lane == 0) { wv[w] = v; wi[w] = idx; }
            __syncthreads();
            if (tid < 16) {
                float v2 = wv[tid]; int i2 = wi[tid];
                #pragma unroll
                for (int o = 8; o > 0; o >>= 1) {
                    float ov = __shfl_xor_sync(0xffffu, v2, o);
                    int   oi = __shfl_xor_sync(0xffffu, i2, o);
                    if (ov > v2 || (ov == v2 && oi < i2)) { v2 = ov; i2 = oi; }
                }
                if (tid == 0) { swin = i2; tix[pass] = i2; }
            }
            __syncthreads();
            if (mi == swin) { mv = -FLT_MAX; mi = 0x7fffffff; }
        }
    }
    // ---- bottom-8 ----
    {
        float mv = g_cminv[tid];
        int   mi = g_cmini[tid];
        #pragma unroll 1
        for (int pass = 0; pass < 8; pass++) {
            float v = mv; int idx = mi;
            #pragma unroll
            for (int o = 16; o > 0; o >>= 1) {
                float ov = __shfl_xor_sync(0xffffffffu, v, o);
                int   oi = __shfl_xor_sync(0xffffffffu, idx, o);
                if (ov < v || (ov == v && oi < idx)) { v = ov; idx = oi; }
            }
            if (lane == 0) { wv[w] = v; wi[w] = idx; }
            __syncthreads();
            if (tid < 16) {
                float v2 = wv[tid]; int i2 = wi[tid];
                #pragma unroll
                for (int o = 8; o > 0; o >>= 1) {
                    float ov = __shfl_xor_sync(0xffffu, v2, o);
                    int   oi = __shfl_xor_sync(0xffffu, i2, o);
                    if (ov < v2 || (ov == v2 && oi < i2)) { v2 = ov; i2 = oi; }
                }
                if (tid == 0) { swin = i2; tix[8 + pass] = i2; }
            }
            __syncthreads();
            if (mi == swin) { mv = FLT_MAX; mi = 0x7fffffff; }
        }
    }

    // ---- instance head: warp w -> row w (both classes) ----
    {
        int idx = tix[w];
        const float* hr = h + (size_t)idx * NCOMP;
        float a0 = 0.f, a1 = 0.f;
        for (int d = lane; d < NCOMP; d += 32) {
            float hv = hr[d];
            a0 = fmaf(hv, W_ins[2 * d + 0], a0);
            a1 = fmaf(hv, W_ins[2 * d + 1], a1);
        }
        #pragma unroll
        for (int o = 16; o > 0; o >>= 1) {
            a0 += __shfl_xor_sync(0xffffffffu, a0, o);
            a1 += __shfl_xor_sync(0xffffffffu, a1, o);
        }
        if (lane == 0) {
            s_logit[w * 2 + 0] = a0 + b_ins[0];
            s_logit[w * 2 + 1] = a1 + b_ins[1];
        }
    }
    if (w < 2) {
        int c = w;
        float acc = 0.f;
        for (int d = lane; d < NCOMP; d += 32)
            acc = fmaf(g_agg[c * NCOMP + d], W_bag[d], acc);
        #pragma unroll
        for (int o = 16; o > 0; o >>= 1)
            acc += __shfl_xor_sync(0xffffffffu, acc, o);
        if (lane == 0) s_slide[c] = acc + b_bag[0];
    }
    __syncthreads();

    if (tid < 16) {
        float l0 = s_logit[tid * 2 + 0];
        float l1 = s_logit[tid * 2 + 1];
        out[OFF_IU + tid * 2 + 0] = l0;
        out[OFF_IU + tid * 2 + 1] = l1;
        float m = fmaxf(l0, l1);
        float e0 = expf(l0 - m), e1 = expf(l1 - m);
        float inv = 1.0f / (e0 + e1);
        out[OFF_IL + tid * 2 + 0] = e0 * inv;
        out[OFF_IL + tid * 2 + 1] = e1 * inv;
        out[OFF_LAB + tid] = (tid < 8) ? 1.0f : 0.0f;
    }
    if (tid == 0) {
        float s0 = s_slide[0], s1 = s_slide[1];
        out[OFF_SS + 0] = s0;
        out[OFF_SS + 1] = s1;
        float m = fmaxf(s0, s1);
        float e0 = expf(s0 - m), e1 = expf(s1 - m);
        float inv = 1.0f / (e0 + e1);
        out[OFF_YP + 0] = e0 * inv;
        out[OFF_YP + 1] = e1 * inv;
        out[OFF_YH] = (s1 > s0) ? 1.0f : 0.0f;
    }
}

// ---------------------------------------------------------------------------
// kernel_launch
// ---------------------------------------------------------------------------
extern "C" void kernel_launch(void* const* d_in, const int* in_sizes, int n_in,
                              void* d_out, int out_size)
{
    const float* x   = (const float*)d_in[0];
    const int*   sl  = (const int*)  d_in[1];
    const float* Wc  = (const float*)d_in[2];
    const float* bc  = (const float*)d_in[3];
    const float* W1  = (const float*)d_in[4];
    const float* b1  = (const float*)d_in[5];
    const float* W2  = (const float*)d_in[6];
    const float* b2  = (const float*)d_in[7];
    const float* W3  = (const float*)d_in[8];
    const float* b3  = (const float*)d_in[9];
    const float* Wi  = (const float*)d_in[10];
    const float* bi  = (const float*)d_in[11];
    const float* Wb  = (const float*)d_in[12];
    const float* bb  = (const float*)d_in[13];

    float* out = (float*)d_out;
    float* h   = out + OFF_H;

    const int SMEM1 = 3 * (128 * 128 + 256 * 128);  // 144 KB
    const int SMEM2 = 3 * (64 * 128 + 512 * 128);   // 216 KB
    cudaFuncSetAttribute(gemm1, cudaFuncAttributeMaxDynamicSharedMemorySize, SMEM1);
    cudaFuncSetAttribute(gemm2, cudaFuncAttributeMaxDynamicSharedMemorySize, SMEM2);

    prep_kernel<<<769, 256>>>(Wc, W1, W2);

    // h = relu(x @ Wc + bc)
    gemm1<<<dim3(2, M_PAD / 128), 512, SMEM1>>>(x, bc, out);

    // gated attention GEMM, fully fused softmax epilogue
    gemm2<<<M_PAD / 64, 512, SMEM2>>>(b1, b2, W3, b3, sl, out);

    // slide_agg (vectorized) + topk stage 1, one launch
    post_kernel<<<AGG_BLOCKS + TK_BLOCKS, 256>>>(out + OFF_A);

    // register/shuffle topk stage2 + instance head + slide score
    topk_final<<<1, 512>>>(Wi, bi, Wb, bb, h, out);
}

// round 15
// speedup vs baseline: 1.0348x; 1.0029x over previous
#include <cuda_runtime.h>
#include <cuda_fp16.h>
#include <math.h>
#include <float.h>
#include <stdint.h>

// ---------------------------------------------------------------------------
// Problem constants
// ---------------------------------------------------------------------------
#define M_BAG   100000
#define M_PAD   100096          // 782 * 128 = 1564 * 64
#define NFEAT   1024
#define NCOMP   512
#define NHID    256

// Output layout (flattened reference tuple, fp32)
#define OFF_ATT   0u
#define OFF_A     200000u
#define OFF_H     400000u
#define OFF_LAB   51600000u
#define OFF_IU    51600016u
#define OFF_IL    51600048u
#define OFF_SS    51600080u
#define OFF_YP    51600082u
#define OFF_YH    51600084u

// ---------------------------------------------------------------------------
// Device scratch (static globals; allocation-free per harness rules)
// ---------------------------------------------------------------------------
__device__ __half g_hh[(size_t)M_PAD * NCOMP];    // h in fp16 (padded rows zero)
__device__ __half g_Wct[(size_t)NCOMP * NFEAT];   // Wc^T  [512][1024]
__device__ __half g_Wt12[(size_t)NCOMP * NCOMP];  // interleaved [W1|W2]^T [512][512]
__device__ float  g_AI[M_BAG];
__device__ float  g_agg[2 * NCOMP];
#define TK_BLOCKS 64
#define TK_CHUNK  1568
#define AGG_BLOCKS 391
__device__ float  g_cmaxv[TK_BLOCKS * 8];
__device__ int    g_cmaxi[TK_BLOCKS * 8];
__device__ float  g_cminv[TK_BLOCKS * 8];
__device__ int    g_cmini[TK_BLOCKS * 8];

// ---------------------------------------------------------------------------
// PTX helpers (sm_80+ features only: mma.sync / ldmatrix / cp.async)
// ---------------------------------------------------------------------------
__device__ __forceinline__ uint32_t smem_u32(const void* p) {
    uint32_t a;
    asm("{ .reg .u64 t; cvta.to.shared.u64 t, %1; cvt.u32.u64 %0, t; }"
        : "=r"(a) : "l"(p));
    return a;
}

#define CPASYNC16(sa, gp) \
    asm volatile("cp.async.cg.shared.global [%0], [%1], 16;" \
                 :: "r"(sa), "l"(gp))
#define CPCOMMIT() asm volatile("cp.async.commit_group;")
template<int N> __device__ __forceinline__ void cp_wait() {
    asm volatile("cp.async.wait_group %0;" :: "n"(N));
}

__device__ __forceinline__ void ldsm4(uint32_t& r0, uint32_t& r1,
                                      uint32_t& r2, uint32_t& r3, uint32_t a) {
    asm volatile("ldmatrix.sync.aligned.m8n8.x4.shared.b16 {%0,%1,%2,%3}, [%4];"
                 : "=r"(r0), "=r"(r1), "=r"(r2), "=r"(r3) : "r"(a));
}

__device__ __forceinline__ void mma16816(float* c, const uint32_t* a,
                                         uint32_t b0, uint32_t b1) {
    asm volatile(
        "mma.sync.aligned.m16n8k16.row.col.f32.f16.f16.f32 "
        "{%0,%1,%2,%3}, {%4,%5,%6,%7}, {%8,%9}, {%0,%1,%2,%3};"
        : "+f"(c[0]), "+f"(c[1]), "+f"(c[2]), "+f"(c[3])
        : "r"(a[0]), "r"(a[1]), "r"(a[2]), "r"(a[3]), "r"(b0), "r"(b1));
}

__device__ __forceinline__ float tanha(float x) {
    float y; asm("tanh.approx.f32 %0, %1;" : "=f"(y) : "f"(x)); return y;
}

// ---------------------------------------------------------------------------
// Prep: coalesced tiled transposes (Wc^T, interleaved [W1|W2]^T) + zero g_agg
// grid = 769 blocks x 256 threads
// ---------------------------------------------------------------------------
__global__ __launch_bounds__(256)
void prep_kernel(const float* __restrict__ Wc,
                 const float* __restrict__ W1,
                 const float* __restrict__ W2)
{
    __shared__ float s[32][33];
    int b = blockIdx.x;
    int t = threadIdx.x;
    int r = t >> 5, c = t & 31;

    if (b < 512) {                         // Wc [1024x512] -> Wct [512][1024]
        int k0 = (b & 31) * 32;
        int n0 = (b >> 5) * 32;
        #pragma unroll
        for (int rr = 0; rr < 4; rr++)
            s[r + rr * 8][c] = Wc[(size_t)(k0 + r + rr * 8) * NCOMP + n0 + c];
        __syncthreads();
        #pragma unroll
        for (int rr = 0; rr < 4; rr++) {
            int nr = r + rr * 8;
            g_Wct[(size_t)(n0 + nr) * NFEAT + k0 + c] = __float2half_rn(s[c][nr]);
        }
    } else if (b < 768) {                  // W1/W2 [512x256] -> interleaved Wt12
        int t2 = b - 512;
        int p  = t2 & 1;
        int tile = t2 >> 1;
        int k0 = (tile & 15) * 32;
        int j0 = (tile >> 4) * 32;
        const float* W = p ? W2 : W1;
        #pragma unroll
        for (int rr = 0; rr < 4; rr++)
            s[r + rr * 8][c] = W[(size_t)(k0 + r + rr * 8) * NHID + j0 + c];
        __syncthreads();
        #pragma unroll
        for (int rr = 0; rr < 4; rr++) {
            int jr = r + rr * 8;
            g_Wt12[(size_t)(2 * (j0 + jr) + p) * NCOMP + k0 + c]
                = __float2half_rn(s[c][jr]);
        }
    } else {                               // zero slide_agg accumulator
        for (int i = t; i < 2 * NCOMP; i += 256) g_agg[i] = 0.0f;
    }
}

// ---------------------------------------------------------------------------
// GEMM1: h = relu(x @ Wc + bc).  BM=128, BN=256, K=1024, 512 threads
// (16 warps, 4x4 of 32x64), 3-stage pipeline, SW128 swizzle.
// A: fp32 LDG -> reg convert -> STS (conversion fused).
// Epilogue writes h fp32 (out) + fp16 (g_hh).
// ---------------------------------------------------------------------------
__global__ void __launch_bounds__(512, 1)
gemm1(const float* __restrict__ x, const float* __restrict__ bc,
      float* __restrict__ out)
{
    constexpr int K      = NFEAT;
    constexpr int NT     = K / 64;
    constexpr int ABYTES = 128 * 128;
    constexpr int STRIDE = ABYTES + 256 * 128;      // 48 KB / stage

    extern __shared__ __align__(1024) char smem[];

    const int tid  = threadIdx.x;
    const int lane = tid & 31;
    const int wid  = tid >> 5;
    const int wm   = (wid >> 2) * 32;
    const int wn   = (wid & 3) * 64;
    const int rowBase = blockIdx.y * 128;
    const int colBase = blockIdx.x * 256;

    const uint32_t sbase = smem_u32(smem);

    const int aRowOff = (lane & 7) + ((lane >> 3) & 1) * 8;
    const int aCk     = (lane >> 4) & 1;
    const int bRowOff = (lane & 7) + ((lane >> 4) & 1) * 8;
    const int bCk     = (lane >> 3) & 1;

    float acc[2][8][4];
    #pragma unroll
    for (int mi = 0; mi < 2; mi++)
        #pragma unroll
        for (int ni = 0; ni < 8; ni++)
            #pragma unroll
            for (int q = 0; q < 4; q++) acc[mi][ni][q] = 0.0f;

    auto load_b = [&](int kt, int stg) {
        const uint32_t sB = sbase + stg * STRIDE + ABYTES;
        const __half* Bg = g_Wct + (size_t)colBase * K + kt * 64;
        #pragma unroll
        for (int i = 0; i < 4; i++) {
            int lin = tid + 512 * i;
            int row = lin >> 3, seg = lin & 7;
            uint32_t sa = sB + row * 128 + ((seg ^ (row & 7)) << 4);
            CPASYNC16(sa, Bg + (size_t)row * K + seg * 8);
        }
    };

    float4 areg[4];
    auto ldg_a = [&](int kt) {
        #pragma unroll
        for (int i = 0; i < 2; i++) {
            int lin = tid + 512 * i;
            int row = lin >> 3, seg = lin & 7;
            int gr  = rowBase + row;
            if (gr < M_BAG) {
                const float4* p = reinterpret_cast<const float4*>(
                    x + (size_t)gr * K + kt * 64 + seg * 8);
                areg[2 * i]     = p[0];
                areg[2 * i + 1] = p[1];
            } else {
                areg[2 * i]     = make_float4(0.f, 0.f, 0.f, 0.f);
                areg[2 * i + 1] = make_float4(0.f, 0.f, 0.f, 0.f);
            }
        }
    };
    auto sts_a = [&](int stg) {
        char* sA = smem + stg * STRIDE;
        #pragma unroll
        for (int i = 0; i < 2; i++) {
            int lin = tid + 512 * i;
            int row = lin >> 3, seg = lin & 7;
            float4 a = areg[2 * i], b = areg[2 * i + 1];
            __half2 h0 = __floats2half2_rn(a.x, a.y);
            __half2 h1 = __floats2half2_rn(a.z, a.w);
            __half2 h2 = __floats2half2_rn(b.x, b.y);
            __half2 h3 = __floats2half2_rn(b.z, b.w);
            uint4 v;
            v.x = *reinterpret_cast<uint32_t*>(&h0);
            v.y = *reinterpret_cast<uint32_t*>(&h1);
            v.z = *reinterpret_cast<uint32_t*>(&h2);
            v.w = *reinterpret_cast<uint32_t*>(&h3);
            *reinterpret_cast<uint4*>(sA + row * 128 + ((seg ^ (row & 7)) << 4)) = v;
        }
    };

    ldg_a(0); load_b(0, 0); CPCOMMIT(); sts_a(0);
    ldg_a(1); load_b(1, 1); CPCOMMIT(); sts_a(1);

    for (int kt = 0; kt < NT; kt++) {
        if (kt == NT - 1) cp_wait<0>(); else cp_wait<1>();
        __syncthreads();

        const bool pre = (kt + 2 < NT);
        const int  nstg = (kt + 2) % 3;
        if (pre) {
            ldg_a(kt + 2);
            load_b(kt + 2, nstg);
            CPCOMMIT();
        }

        const uint32_t sA = sbase + (kt % 3) * STRIDE;
        const uint32_t sB = sA + ABYTES;

        #pragma unroll
        for (int ks = 0; ks < 4; ks++) {
            uint32_t a[2][4];
            #pragma unroll
            for (int mi = 0; mi < 2; mi++) {
                int row = wm + mi * 16 + aRowOff;
                uint32_t ad = sA + row * 128 +
                              (((ks * 2 + aCk) ^ (row & 7)) << 4);
                ldsm4(a[mi][0], a[mi][1], a[mi][2], a[mi][3], ad);
            }
            #pragma unroll
            for (int np = 0; np < 4; np++) {
                uint32_t b0, b1r, b2r, b3r;
                int row = wn + np * 16 + bRowOff;
                uint32_t bd = sB + row * 128 +
                              (((ks * 2 + bCk) ^ (row & 7)) << 4);
                ldsm4(b0, b1r, b2r, b3r, bd);
                #pragma unroll
                for (int mi = 0; mi < 2; mi++) {
                    mma16816(acc[mi][2 * np + 0], a[mi], b0, b1r);
                    mma16816(acc[mi][2 * np + 1], a[mi], b2r, b3r);
                }
            }
        }

        if (pre) sts_a(nstg);
    }

    // epilogue: bias + relu, dual store
    const int qrow = lane >> 2;
    const int qcol = (lane & 3) * 2;
    float* h32 = out + OFF_H;
    float2 bias_v[8];
    #pragma unroll
    for (int ni = 0; ni < 8; ni++) {
        int col = colBase + wn + ni * 8 + qcol;
        bias_v[ni] = *reinterpret_cast<const float2*>(bc + col);
    }
    #pragma unroll
    for (int mi = 0; mi < 2; mi++) {
        int r0 = rowBase + wm + mi * 16 + qrow;
        int r1 = r0 + 8;
        #pragma unroll
        for (int ni = 0; ni < 8; ni++) {
            int col = colBase + wn + ni * 8 + qcol;
            float v0 = fmaxf(acc[mi][ni][0] + bias_v[ni].x, 0.f);
            float v1 = fmaxf(acc[mi][ni][1] + bias_v[ni].y, 0.f);
            float v2 = fmaxf(acc[mi][ni][2] + bias_v[ni].x, 0.f);
            float v3 = fmaxf(acc[mi][ni][3] + bias_v[ni].y, 0.f);
            if (r0 < M_BAG) {
                *reinterpret_cast<float2*>(h32 + (size_t)r0 * NCOMP + col)
                    = make_float2(v0, v1);
                __half2 p = __floats2half2_rn(v0, v1);
                *reinterpret_cast<__half2*>(g_hh + (size_t)r0 * NCOMP + col) = p;
            }
            if (r1 < M_BAG) {
                *reinterpret_cast<float2*>(h32 + (size_t)r1 * NCOMP + col)
                    = make_float2(v2, v3);
                __half2 p = __floats2half2_rn(v2, v3);
                *reinterpret_cast<__half2*>(g_hh + (size_t)r1 * NCOMP + col) = p;
            }
        }
    }
}

// ---------------------------------------------------------------------------
// GEMM2: fully fused gated attention. BM=64, BN=512 (full N per CTA),
// K=512, 512 threads (16 warps, 2x8 of 32x64), 3-stage pipeline.
// Epilogue: a = tanh(t1)*sigmoid(t2) (MUFU), att = a@W3 + b3 reduced in
// smem, softmax, writes att_score / A / A_I directly. No global atomics.
// ---------------------------------------------------------------------------
__global__ void __launch_bounds__(512, 1)
gemm2(const float* __restrict__ b1, const float* __restrict__ b2,
      const float* __restrict__ W3, const float* __restrict__ b3,
      const int* __restrict__ sl, float* __restrict__ out)
{
    constexpr int K      = NCOMP;
    constexpr int NT     = K / 64;                  // 8
    constexpr int ABYTES = 64 * 128;                // 8 KB
    constexpr int STRIDE = ABYTES + 512 * 128;      // 72 KB / stage

    extern __shared__ __align__(1024) char smem[];

    const int tid  = threadIdx.x;
    const int lane = tid & 31;
    const int wid  = tid >> 5;
    const int wm   = (wid >> 3) * 32;    // 2 warp rows of 32
    const int wn   = (wid & 7) * 64;     // 8 warp cols of 64
    const int rowBase = blockIdx.x * 64;

    const uint32_t sbase = smem_u32(smem);

    const int aRowOff = (lane & 7) + ((lane >> 3) & 1) * 8;
    const int aCk     = (lane >> 4) & 1;
    const int bRowOff = (lane & 7) + ((lane >> 4) & 1) * 8;
    const int bCk     = (lane >> 3) & 1;

    float acc[2][8][4];
    #pragma unroll
    for (int mi = 0; mi < 2; mi++)
        #pragma unroll
        for (int ni = 0; ni < 8; ni++)
            #pragma unroll
            for (int q = 0; q < 4; q++) acc[mi][ni][q] = 0.0f;

    auto load_b = [&](int kt, int stg) {
        const uint32_t sB = sbase + stg * STRIDE + ABYTES;
        const __half* Bg = g_Wt12 + kt * 64;
        #pragma unroll
        for (int i = 0; i < 8; i++) {            // 512 rows x 8 segs / 512 thr
            int lin = tid + 512 * i;
            int row = lin >> 3, seg = lin & 7;
            uint32_t sa = sB + row * 128 + ((seg ^ (row & 7)) << 4);
            CPASYNC16(sa, Bg + (size_t)row * K + seg * 8);
        }
    };
    auto cp_a = [&](int kt, int stg) {
        const uint32_t sA = sbase + stg * STRIDE;
        const __half* Ag = g_hh + (size_t)rowBase * K + kt * 64;
        int row = tid >> 3, seg = tid & 7;       // 64 rows x 8 segs = 512
        uint32_t sa = sA + row * 128 + ((seg ^ (row & 7)) << 4);
        CPASYNC16(sa, Ag + (size_t)row * K + seg * 8);
    };

    cp_a(0, 0); load_b(0, 0); CPCOMMIT();
    cp_a(1, 1); load_b(1, 1); CPCOMMIT();

    for (int kt = 0; kt < NT; kt++) {
        if (kt == NT - 1) cp_wait<0>(); else cp_wait<1>();
        __syncthreads();

        const bool pre = (kt + 2 < NT);
        const int  nstg = (kt + 2) % 3;
        if (pre) {
            cp_a(kt + 2, nstg);
            load_b(kt + 2, nstg);
            CPCOMMIT();
        }

        const uint32_t sA = sbase + (kt % 3) * STRIDE;
        const uint32_t sB = sA + ABYTES;

        #pragma unroll
        for (int ks = 0; ks < 4; ks++) {
            uint32_t a[2][4];
            #pragma unroll
            for (int mi = 0; mi < 2; mi++) {
                int row = wm + mi * 16 + aRowOff;
                uint32_t ad = sA + row * 128 +
                              (((ks * 2 + aCk) ^ (row & 7)) << 4);
                ldsm4(a[mi][0], a[mi][1], a[mi][2], a[mi][3], ad);
            }
            #pragma unroll
            for (int np = 0; np < 4; np++) {
                uint32_t b0, b1r, b2r, b3r;
                int row = wn + np * 16 + bRowOff;
                uint32_t bd = sB + row * 128 +
                              (((ks * 2 + bCk) ^ (row & 7)) << 4);
                ldsm4(b0, b1r, b2r, b3r, bd);
                #pragma unroll
                for (int mi = 0; mi < 2; mi++) {
                    mma16816(acc[mi][2 * np + 0], a[mi], b0, b1r);
                    mma16816(acc[mi][2 * np + 1], a[mi], b2r, b3r);
                }
            }
        }
    }

    // ---- fused epilogue: gate + a@W3 reduced in smem, softmax, outputs ----
    const int qrow = lane >> 2;
    const int qcol = (lane & 3) * 2;
    float* satt = reinterpret_cast<float*>(smem);   // 64 rows x 2 classes

    __syncthreads();
    if (tid < 128) satt[tid] = 0.0f;
    __syncthreads();

    float b1v[8], b2v[8], w3x[8], w3y[8];
    #pragma unroll
    for (int ni = 0; ni < 8; ni++) {
        int j = (wn + ni * 8 + qcol) >> 1;
        b1v[ni] = b1[j];
        b2v[ni] = b2[j];
        float2 w = reinterpret_cast<const float2*>(W3)[j];
        w3x[ni] = w.x; w3y[ni] = w.y;
    }
    #pragma unroll
    for (int mi = 0; mi < 2; mi++) {
        int lr0 = wm + mi * 16 + qrow;
        int lr1 = lr0 + 8;
        float s00 = 0.f, s01 = 0.f, s10 = 0.f, s11 = 0.f;
        #pragma unroll
        for (int ni = 0; ni < 8; ni++) {
            float t1 = acc[mi][ni][0] + b1v[ni];
            float t2 = acc[mi][ni][1] + b2v[ni];
            float a0 = tanha(t1) * fmaf(tanha(0.5f * t2), 0.5f, 0.5f);
            s00 = fmaf(a0, w3x[ni], s00);
            s01 = fmaf(a0, w3y[ni], s01);
            float u1 = acc[mi][ni][2] + b1v[ni];
            float u2 = acc[mi][ni][3] + b2v[ni];
            float a1 = tanha(u1) * fmaf(tanha(0.5f * u2), 0.5f, 0.5f);
            s10 = fmaf(a1, w3x[ni], s10);
            s11 = fmaf(a1, w3y[ni], s11);
        }
        #pragma unroll
        for (int o = 1; o <= 2; o <<= 1) {
            s00 += __shfl_xor_sync(0xffffffffu, s00, o);
            s01 += __shfl_xor_sync(0xffffffffu, s01, o);
            s10 += __shfl_xor_sync(0xffffffffu, s10, o);
            s11 += __shfl_xor_sync(0xffffffffu, s11, o);
        }
        if ((lane & 3) == 0) {
            atomicAdd(&satt[2 * lr0 + 0], s00);
            atomicAdd(&satt[2 * lr0 + 1], s01);
            atomicAdd(&satt[2 * lr1 + 0], s10);
            atomicAdd(&satt[2 * lr1 + 1], s11);
        }
    }
    __syncthreads();

    if (tid < 64) {
        int r = rowBase + tid;
        if (r < M_BAG) {
            float s0 = satt[2 * tid + 0] + b3[0];
            float s1 = satt[2 * tid + 1] + b3[1];
            out[OFF_ATT + 2 * r + 0] = s0;
            out[OFF_ATT + 2 * r + 1] = s1;
            float m  = fmaxf(s0, s1);
            float e0 = expf(s0 - m), e1 = expf(s1 - m);
            float inv = 1.0f / (e0 + e1);
            float A0 = e0 * inv, A1 = e1 * inv;
            out[OFF_A + 2 * r + 0] = A0;
            out[OFF_A + 2 * r + 1] = A1;
            g_AI[r] = (sl[0] != 0) ? A1 : A0;
        }
    }
}

// ---------------------------------------------------------------------------
// Post (512 threads): agg (blocks 0..390, 256 rows, vectorized uint4 loads,
// 8 row-phases, smem pre-reduction) + topk stage1 (blocks 391..454).
// ---------------------------------------------------------------------------
__global__ __launch_bounds__(512)
void post_kernel(const float* __restrict__ Amat)
{
    int b = blockIdx.x;
    int tid = threadIdx.x;

    if (b < AGG_BLOCKS) {
        // ---- slide_agg = A^T @ h (fp16) ----
        // thread: cg = tid & 63 -> 8 columns; ro = tid >> 6 (0..7) row phase
        __shared__ float sred[2 * NCOMP];      // 4 KB
        const int cg = tid & 63;
        const int ro = tid >> 6;
        int r0 = b * 256;
        int r1 = min(r0 + 256, M_BAG);

        float c0[8], c1[8];
        #pragma unroll
        for (int k = 0; k < 8; k++) { c0[k] = 0.f; c1[k] = 0.f; }

        const float2* Av2 = reinterpret_cast<const float2*>(Amat);
        #pragma unroll 4
        for (int n = r0 + ro; n < r1; n += 8) {
            float2 Av = Av2[n];
            uint4 hv = *reinterpret_cast<const uint4*>(
                g_hh + (size_t)n * NCOMP + cg * 8);
            __half2 p0 = *reinterpret_cast<__half2*>(&hv.x);
            __half2 p1 = *reinterpret_cast<__half2*>(&hv.y);
            __half2 p2 = *reinterpret_cast<__half2*>(&hv.z);
            __half2 p3 = *reinterpret_cast<__half2*>(&hv.w);
            float f[8];
            f[0] = __low2float(p0); f[1] = __high2float(p0);
            f[2] = __low2float(p1); f[3] = __high2float(p1);
            f[4] = __low2float(p2); f[5] = __high2float(p2);
            f[6] = __low2float(p3); f[7] = __high2float(p3);
            #pragma unroll
            for (int k = 0; k < 8; k++) {
                c0[k] = fmaf(Av.x, f[k], c0[k]);
                c1[k] = fmaf(Av.y, f[k], c1[k]);
            }
        }

        // smem pre-reduction (<=8-way contention per address)
        for (int i = tid; i < 2 * NCOMP; i += 512) sred[i] = 0.0f;
        __syncthreads();
        #pragma unroll
        for (int k = 0; k < 8; k++) {
            atomicAdd(&sred[cg * 8 + k],         c0[k]);
            atomicAdd(&sred[NCOMP + cg * 8 + k], c1[k]);
        }
        __syncthreads();
        #pragma unroll
        for (int i = 0; i < 2; i++) {
            int idx = tid * 2 + i;
            atomicAdd(&g_agg[idx], sred[idx]);
        }
        return;
    }

    // ---- topk stage 1 (512 threads) ----
    __shared__ float svmax[TK_CHUNK];
    __shared__ float svmin[TK_CHUNK];
    __shared__ float rv[512];
    __shared__ int   ri[512];
    int blk = b - AGG_BLOCKS;
    int base = blk * TK_CHUNK;

    for (int i = tid; i < TK_CHUNK; i += 512) {
        int g = base + i;
        float v = (g < M_BAG) ? g_AI[g] : 0.0f;
        svmax[i] = (g < M_BAG) ? v : -FLT_MAX;
        svmin[i] = (g < M_BAG) ? v :  FLT_MAX;
    }
    __syncthreads();

    for (int pass = 0; pass < 8; pass++) {
        float bv = -FLT_MAX; int bi = 0x7fffffff;
        for (int i = tid; i < TK_CHUNK; i += 512) {
            float v = svmax[i]; int g = base + i;
            if (v > bv || (v == bv && g < bi)) { bv = v; bi = g; }
        }
        rv[tid] = bv; ri[tid] = bi;
        __syncthreads();
        for (int s = 256; s > 0; s >>= 1) {
            if (tid < s) {
                float ov = rv[tid + s]; int oi = ri[tid + s];
                if (ov > rv[tid] || (ov == rv[tid] && oi < ri[tid])) { rv[tid] = ov; ri[tid] = oi; }
            }
            __syncthreads();
        }
        if (tid == 0) {
            g_cmaxv[blk * 8 + pass] = rv[0];
            g_cmaxi[blk * 8 + pass] = ri[0];
            svmax[ri[0] - base] = -FLT_MAX;
        }
        __syncthreads();
    }
    for (int pass = 0; pass < 8; pass++) {
        float bv = FLT_MAX; int bi = 0x7fffffff;
        for (int i = tid; i < TK_CHUNK; i += 512) {
            float v = svmin[i]; int g = base + i;
            if (v < bv || (v == bv && g < bi)) { bv = v; bi = g; }
        }
        rv[tid] = bv; ri[tid] = bi;
        __syncthreads();
        for (int s = 256; s > 0; s >>= 1) {
            if (tid < s) {
                float ov = rv[tid + s]; int oi = ri[tid + s];
                if (ov < rv[tid] || (ov == rv[tid] && oi < ri[tid])) { rv[tid] = ov; ri[tid] = oi; }
            }
            __syncthreads();
        }
        if (tid == 0) {
            g_cminv[blk * 8 + pass] = rv[0];
            g_cmini[blk * 8 + pass] = ri[0];
            svmin[ri[0] - base] = FLT_MAX;
        }
        __syncthreads();
    }
}

// ---------------------------------------------------------------------------
// topk_final: register-resident warp-shuffle selection (2 barriers/pass)
// + instance head + slide score.  512 threads.
// ---------------------------------------------------------------------------
__global__ __launch_bounds__(512)
void topk_final(const float* __restrict__ W_ins, const float* __restrict__ b_ins,
                const float* __restrict__ W_bag, const float* __restrict__ b_bag,
                const float* __restrict__ h, float* __restrict__ out)
{
    __shared__ float wv[16];
    __shared__ int   wi[16];
    __shared__ int   swin;
    __shared__ int   tix[16];
    __shared__ float s_logit[32];
    __shared__ float s_slide[2];
    int tid  = threadIdx.x;
    int lane = tid & 31;
    int w    = tid >> 5;

    // ---- top-8: each thread owns one candidate in registers ----
    {
        float mv = g_cmaxv[tid];
        int   mi = g_cmaxi[tid];
        #pragma unroll 1
        for (int pass = 0; pass < 8; pass++) {
            float v = mv; int idx = mi;
            #pragma unroll
            for (int o = 16; o > 0; o >>= 1) {
                float ov = __shfl_xor_sync(0xffffffffu, v, o);
                int   oi = __shfl_xor_sync(0xffffffffu, idx, o);
                if (ov > v || (ov == v && oi < idx)) { v = ov; idx = oi; }
            }
            if (lane == 0) { wv[w] = v; wi[w] = idx; }
            __syncthreads();
            if (tid < 16) {
                float v2 = wv[tid]; int i2 = wi[tid];
                #pragma unroll
                for (int o = 8; o > 0; o >>= 1) {
                    float ov = __shfl_xor_sync(0xffffu, v2, o);
                    int   oi = __shfl_xor_sync(0xffffu, i2, o);
                    if (ov > v2 || (ov == v2 && oi < i2)) { v2 = ov; i2 = oi; }
                }
                if (tid == 0) { swin = i2; tix[pass] = i2; }
            }
            __syncthreads();
            if (mi == swin) { mv = -FLT_MAX; mi = 0x7fffffff; }
        }
    }
    // ---- bottom-8 ----
    {
        float mv = g_cminv[tid];
        int   mi = g_cmini[tid];
        #pragma unroll 1
        for (int pass = 0; pass < 8; pass++) {
            float v = mv; int idx = mi;
            #pragma unroll
            for (int o = 16; o > 0; o >>= 1) {
                float ov = __shfl_xor_sync(0xffffffffu, v, o);
                int   oi = __shfl_xor_sync(0xffffffffu, idx, o);
                if (ov < v || (ov == v && oi < idx)) { v = ov; idx = oi; }
            }
            if (lane == 0) { wv[w] = v; wi[w] = idx; }
            __syncthreads();
            if (tid < 16) {
                float v2 = wv[tid]; int i2 = wi[tid];
                #pragma unroll
                for (int o = 8; o > 0; o >>= 1) {
                    float ov = __shfl_xor_sync(0xffffu, v2, o);
                    int   oi = __shfl_xor_sync(0xffffu, i2, o);
                    if (ov < v2 || (ov == v2 && oi < i2)) { v2 = ov; i2 = oi; }
                }
                if (tid == 0) { swin = i2; tix[8 + pass] = i2; }
            }
            __syncthreads();
            if (mi == swin) { mv = FLT_MAX; mi = 0x7fffffff; }
        }
    }

    // ---- instance head: warp w -> row w (both classes) ----
    {
        int idx = tix[w];
        const float* hr = h + (size_t)idx * NCOMP;
        float a0 = 0.f, a1 = 0.f;
        for (int d = lane; d < NCOMP; d += 32) {
            float hv = hr[d];
            a0 = fmaf(hv, W_ins[2 * d + 0], a0);
            a1 = fmaf(hv, W_ins[2 * d + 1], a1);
        }
        #pragma unroll
        for (int o = 16; o > 0; o >>= 1) {
            a0 += __shfl_xor_sync(0xffffffffu, a0, o);
            a1 += __shfl_xor_sync(0xffffffffu, a1, o);
        }
        if (lane == 0) {
            s_logit[w * 2 + 0] = a0 + b_ins[0];
            s_logit[w * 2 + 1] = a1 + b_ins[1];
        }
    }
    if (w < 2) {
        int c = w;
        float acc = 0.f;
        for (int d = lane; d < NCOMP; d += 32)
            acc = fmaf(g_agg[c * NCOMP + d], W_bag[d], acc);
        #pragma unroll
        for (int o = 16; o > 0; o >>= 1)
            acc += __shfl_xor_sync(0xffffffffu, acc, o);
        if (lane == 0) s_slide[c] = acc + b_bag[0];
    }
    __syncthreads();

    if (tid < 16) {
        float l0 = s_logit[tid * 2 + 0];
        float l1 = s_logit[tid * 2 + 1];
        out[OFF_IU + tid * 2 + 0] = l0;
        out[OFF_IU + tid * 2 + 1] = l1;
        float m = fmaxf(l0, l1);
        float e0 = expf(l0 - m), e1 = expf(l1 - m);
        float inv = 1.0f / (e0 + e1);
        out[OFF_IL + tid * 2 + 0] = e0 * inv;
        out[OFF_IL + tid * 2 + 1] = e1 * inv;
        out[OFF_LAB + tid] = (tid < 8) ? 1.0f : 0.0f;
    }
    if (tid == 0) {
        float s0 = s_slide[0], s1 = s_slide[1];
        out[OFF_SS + 0] = s0;
        out[OFF_SS + 1] = s1;
        float m = fmaxf(s0, s1);
        float e0 = expf(s0 - m), e1 = expf(s1 - m);
        float inv = 1.0f / (e0 + e1);
        out[OFF_YP + 0] = e0 * inv;
        out[OFF_YP + 1] = e1 * inv;
        out[OFF_YH] = (s1 > s0) ? 1.0f : 0.0f;
    }
}

// ---------------------------------------------------------------------------
// kernel_launch
// ---------------------------------------------------------------------------
extern "C" void kernel_launch(void* const* d_in, const int* in_sizes, int n_in,
                              void* d_out, int out_size)
{
    const float* x   = (const float*)d_in[0];
    const int*   sl  = (const int*)  d_in[1];
    const float* Wc  = (const float*)d_in[2];
    const float* bc  = (const float*)d_in[3];
    const float* W1  = (const float*)d_in[4];
    const float* b1  = (const float*)d_in[5];
    const float* W2  = (const float*)d_in[6];
    const float* b2  = (const float*)d_in[7];
    const float* W3  = (const float*)d_in[8];
    const float* b3  = (const float*)d_in[9];
    const float* Wi  = (const float*)d_in[10];
    const float* bi  = (const float*)d_in[11];
    const float* Wb  = (const float*)d_in[12];
    const float* bb  = (const float*)d_in[13];

    float* out = (float*)d_out;
    float* h   = out + OFF_H;

    const int SMEM1 = 3 * (128 * 128 + 256 * 128);  // 144 KB
    const int SMEM2 = 3 * (64 * 128 + 512 * 128);   // 216 KB
    cudaFuncSetAttribute(gemm1, cudaFuncAttributeMaxDynamicSharedMemorySize, SMEM1);
    cudaFuncSetAttribute(gemm2, cudaFuncAttributeMaxDynamicSharedMemorySize, SMEM2);

    prep_kernel<<<769, 256>>>(Wc, W1, W2);

    // h = relu(x @ Wc + bc)
    gemm1<<<dim3(2, M_PAD / 128), 512, SMEM1>>>(x, bc, out);

    // gated attention GEMM, fully fused softmax epilogue
    gemm2<<<M_PAD / 64, 512, SMEM2>>>(b1, b2, W3, b3, sl, out);

    // slide_agg (512 threads, 8 row-phases) + topk stage 1, one launch
    post_kernel<<<AGG_BLOCKS + TK_BLOCKS, 512>>>(out + OFF_A);

    // register/shuffle topk stage2 + instance head + slide score
    topk_final<<<1, 512>>>(Wi, bi, Wb, bb, h, out);
}